// round 2
// baseline (speedup 1.0000x reference)
#include <cuda_runtime.h>
#include <cuda_bf16.h>
#include <cstdint>

// Problem constants (shapes fixed by dataset; re-derived at launch)
#define MAX_NODES 100000
#define HID 64

// Scratch (allocation-free rule: __device__ globals). 16B-aligned for float4/red.v4.
__device__ __align__(16) float g_deg[MAX_NODES];
__device__ __align__(16) float g_dinv[MAX_NODES];
__device__ __align__(16) float g_h1[MAX_NODES * HID];    // x @ W1
__device__ __align__(16) float g_agg1[MAX_NODES * HID];  // layer-1 agg, relu'd hidden in place
__device__ __align__(16) float g_h2[MAX_NODES * HID];    // hidden @ W2

// ---------------------------------------------------------------------------
// degree / normalization
// ---------------------------------------------------------------------------
__global__ void deg_init_kernel(float* deg, int N) {
    int i = blockIdx.x * blockDim.x + threadIdx.x;
    if (i < N) deg[i] = 1.0f;  // self-loop contributes 1 to every node's degree
}

__global__ void deg_acc_kernel(const int* __restrict__ dst, float* deg, int E) {
    int i = blockIdx.x * blockDim.x + threadIdx.x;
    if (i < E) atomicAdd(&deg[dst[i]], 1.0f);
}

__global__ void dinv_kernel(const float* __restrict__ deg, float* dinv, int N) {
    int i = blockIdx.x * blockDim.x + threadIdx.x;
    if (i < N) dinv[i] = rsqrtf(deg[i]);  // deg >= 1 always (self-loops)
}

// ---------------------------------------------------------------------------
// GEMM: C[M,64] = A[M,K] @ B[K,64], fp32
// smem-tiled: BM=64, BN=64, BK=32, 256 threads, 4x4 microtile.
// ---------------------------------------------------------------------------
template <int K>
__launch_bounds__(256)
__global__ void gemm64_kernel(const float* __restrict__ A, const float* __restrict__ B,
                              float* __restrict__ C, int M) {
    constexpr int BM = 64, BK = 32;
    __shared__ float As[BK][BM];  // transposed: As[k][m]
    __shared__ float Bs[BK][64];

    const int tid = threadIdx.x;
    const int block_row = blockIdx.x * BM;
    const int tcol = (tid & 15) * 4;   // n offset of 4x4 tile
    const int trow = (tid >> 4) * 4;   // m offset of 4x4 tile

    float acc[4][4] = {};

    for (int k0 = 0; k0 < K; k0 += BK) {
        // A tile (BM x BK = 2048 floats = 512 float4; 2 per thread)
#pragma unroll
        for (int i = 0; i < 2; i++) {
            int idx = tid + i * 256;
            int r = idx >> 3;            // row in tile
            int c4 = (idx & 7) * 4;      // k offset
            int grow = block_row + r;
            float4 v = make_float4(0.f, 0.f, 0.f, 0.f);
            if (grow < M)
                v = *reinterpret_cast<const float4*>(&A[(size_t)grow * K + k0 + c4]);
            As[c4 + 0][r] = v.x; As[c4 + 1][r] = v.y;
            As[c4 + 2][r] = v.z; As[c4 + 3][r] = v.w;
        }
        // B tile (BK x 64 = 2048 floats)
#pragma unroll
        for (int i = 0; i < 2; i++) {
            int idx = tid + i * 256;
            int r = idx >> 4;
            int c4 = (idx & 15) * 4;
            float4 v = *reinterpret_cast<const float4*>(&B[(size_t)(k0 + r) * 64 + c4]);
            *reinterpret_cast<float4*>(&Bs[r][c4]) = v;
        }
        __syncthreads();

#pragma unroll
        for (int k = 0; k < BK; k++) {
            float am[4], bn[4];
#pragma unroll
            for (int i = 0; i < 4; i++) am[i] = As[k][trow + i];
#pragma unroll
            for (int j = 0; j < 4; j++) bn[j] = Bs[k][tcol + j];
#pragma unroll
            for (int i = 0; i < 4; i++)
#pragma unroll
                for (int j = 0; j < 4; j++) acc[i][j] += am[i] * bn[j];
        }
        __syncthreads();
    }

#pragma unroll
    for (int i = 0; i < 4; i++) {
        int grow = block_row + trow + i;
        if (grow < M) {
            float4 v = make_float4(acc[i][0], acc[i][1], acc[i][2], acc[i][3]);
            *reinterpret_cast<float4*>(&C[(size_t)grow * 64 + tcol]) = v;
        }
    }
}

// ---------------------------------------------------------------------------
// zero a float buffer (float4 granularity)
// ---------------------------------------------------------------------------
__global__ void zero_kernel(float4* buf, int count4) {
    int i = blockIdx.x * blockDim.x + threadIdx.x;
    if (i < count4) buf[i] = make_float4(0.f, 0.f, 0.f, 0.f);
}

// ---------------------------------------------------------------------------
// Edge scatter: agg[dst] += h[src] * dinv[src]*dinv[dst]
// 16 threads per edge, each does 4 channels via float4 + red.global.add.v4.f32
// ---------------------------------------------------------------------------
__global__ void scatter_kernel(const int* __restrict__ src,
                               const int* __restrict__ dst,
                               const float* __restrict__ dinv,
                               const float* __restrict__ h,
                               float* __restrict__ agg, int E) {
    long long gid = (long long)blockIdx.x * blockDim.x + threadIdx.x;
    int edge = (int)(gid >> 4);
    int lane = (int)(gid & 15);
    if (edge >= E) return;

    int s = src[edge];
    int d = dst[edge];
    float nrm = dinv[s] * dinv[d];

    float4 v = *reinterpret_cast<const float4*>(&h[(size_t)s * 64 + lane * 4]);
    v.x *= nrm; v.y *= nrm; v.z *= nrm; v.w *= nrm;

    float* p = &agg[(size_t)d * 64 + lane * 4];
    asm volatile("red.global.add.v4.f32 [%0], {%1,%2,%3,%4};"
                 :: "l"(p), "f"(v.x), "f"(v.y), "f"(v.z), "f"(v.w)
                 : "memory");
}

// ---------------------------------------------------------------------------
// Epilogue: out = agg + h * dinv^2 (self-loop) + bias, optional relu. In place.
// ---------------------------------------------------------------------------
template <bool RELU>
__global__ void post_kernel(float* __restrict__ agg, const float* __restrict__ h,
                            const float* __restrict__ dinv, const float* __restrict__ bias,
                            int N) {
    int i = blockIdx.x * blockDim.x + threadIdx.x;
    if (i >= N * 16) return;
    int node = i >> 4;
    int c4 = (i & 15) * 4;
    float di = dinv[node];
    float sl = di * di;

    float4 a = reinterpret_cast<float4*>(agg)[i];
    float4 hv = reinterpret_cast<const float4*>(h)[i];
    float4 bv = *reinterpret_cast<const float4*>(&bias[c4]);

    float r0 = fmaf(hv.x, sl, a.x) + bv.x;
    float r1 = fmaf(hv.y, sl, a.y) + bv.y;
    float r2 = fmaf(hv.z, sl, a.z) + bv.z;
    float r3 = fmaf(hv.w, sl, a.w) + bv.w;
    if (RELU) {
        r0 = fmaxf(r0, 0.f); r1 = fmaxf(r1, 0.f);
        r2 = fmaxf(r2, 0.f); r3 = fmaxf(r3, 0.f);
    }
    reinterpret_cast<float4*>(agg)[i] = make_float4(r0, r1, r2, r3);
}

// ---------------------------------------------------------------------------
// launch
// ---------------------------------------------------------------------------
extern "C" void kernel_launch(void* const* d_in, const int* in_sizes, int n_in,
                              void* d_out, int out_size) {
    const float* x = (const float*)d_in[0];
    const int* edge_index = (const int*)d_in[1];   // int64 in reference -> int32 on device
    const float* W1 = (const float*)d_in[2];
    const float* b1 = (const float*)d_in[3];
    const float* W2 = (const float*)d_in[4];
    const float* b2 = (const float*)d_in[5];
    float* out = (float*)d_out;

    const int IN_CH = 256;
    const int N = in_sizes[0] / IN_CH;     // 100000
    const int E = in_sizes[1] / 2;         // 3200000
    const int* src = edge_index;
    const int* dst = edge_index + E;

    float* deg;   cudaGetSymbolAddress((void**)&deg, g_deg);
    float* dinv;  cudaGetSymbolAddress((void**)&dinv, g_dinv);
    float* h1;    cudaGetSymbolAddress((void**)&h1, g_h1);
    float* agg1;  cudaGetSymbolAddress((void**)&agg1, g_agg1);
    float* h2;    cudaGetSymbolAddress((void**)&h2, g_h2);

    const int T = 256;
    int nBlkN = (N + T - 1) / T;
    int nBlkE = (E + T - 1) / T;
    long long scatterThreads = (long long)E * 16;
    int nBlkS = (int)((scatterThreads + T - 1) / T);
    int count4 = N * 16;                   // N*64 floats as float4
    int nBlkZ = (count4 + T - 1) / T;
    int nBlkP = (N * 16 + T - 1) / T;
    int nBlkG = (N + 63) / 64;

    // normalization
    deg_init_kernel<<<nBlkN, T>>>(deg, N);
    deg_acc_kernel<<<nBlkE, T>>>(dst, deg, E);
    dinv_kernel<<<nBlkN, T>>>(deg, dinv, N);

    // layer 1
    gemm64_kernel<256><<<nBlkG, T>>>(x, W1, h1, N);
    zero_kernel<<<nBlkZ, T>>>((float4*)agg1, count4);
    scatter_kernel<<<nBlkS, T>>>(src, dst, dinv, h1, agg1, E);
    post_kernel<true><<<nBlkP, T>>>(agg1, h1, dinv, b1, N);

    // layer 2
    gemm64_kernel<64><<<nBlkG, T>>>(agg1, W2, h2, N);
    zero_kernel<<<nBlkZ, T>>>((float4*)out, count4);
    scatter_kernel<<<nBlkS, T>>>(src, dst, dinv, h2, out, E);
    post_kernel<false><<<nBlkP, T>>>(out, h2, dinv, b2, N);
}

// round 3
// speedup vs baseline: 1.2923x; 1.2923x over previous
#include <cuda_runtime.h>
#include <cuda_bf16.h>
#include <cstdint>

#define MAX_NODES 100000
#define MAX_EDGES 3200000
#define HID 64

// Scratch (__device__ globals; 16B aligned for float4)
__device__ __align__(16) int   g_cnt[MAX_NODES];
__device__ __align__(16) int   g_off[MAX_NODES + 1];
__device__ __align__(16) int   g_cursor[MAX_NODES];
__device__ __align__(16) int   g_srcs[MAX_EDGES];
__device__ __align__(16) float g_dinv[MAX_NODES];
__device__ __align__(16) float g_h1[MAX_NODES * HID];   // h1' = (x@W1)*dinv (row-scaled)
__device__ __align__(16) float g_hid[MAX_NODES * HID];  // relu'd hidden
__device__ __align__(16) float g_h2[MAX_NODES * HID];   // h2' = (hid@W2)*dinv

// ---------------------------------------------------------------------------
// CSR construction: histogram -> scan -> reorder
// ---------------------------------------------------------------------------
__global__ void zero_cnt_kernel(int* cnt, int N) {
    int i = blockIdx.x * blockDim.x + threadIdx.x;
    if (i < N) cnt[i] = 0;
}

__global__ void hist_kernel(const int* __restrict__ dst, int* cnt, int E) {
    int i = blockIdx.x * blockDim.x + threadIdx.x;
    if (i < E) atomicAdd(&cnt[dst[i]], 1);
}

__global__ void dinv_kernel(const int* __restrict__ cnt, float* dinv, int N) {
    int i = blockIdx.x * blockDim.x + threadIdx.x;
    if (i < N) dinv[i] = rsqrtf((float)cnt[i] + 1.0f);  // +1 self-loop
}

// single-block exclusive scan over N counts (N <= 1024*chunk)
__global__ __launch_bounds__(1024)
void scan_kernel(const int* __restrict__ cnt, int* off, int* cursor, int N, int E) {
    __shared__ int sums[1024];
    const int t = threadIdx.x;
    const int chunk = (N + 1023) / 1024;
    const int beg = t * chunk;
    const int en = min(beg + chunk, N);

    int s = 0;
    for (int i = beg; i < en; i++) s += cnt[i];
    sums[t] = s;
    __syncthreads();
    // Hillis-Steele inclusive scan
    for (int d = 1; d < 1024; d <<= 1) {
        int v = (t >= d) ? sums[t - d] : 0;
        __syncthreads();
        sums[t] += v;
        __syncthreads();
    }
    int run = (t == 0) ? 0 : sums[t - 1];
    for (int i = beg; i < en; i++) {
        off[i] = run;
        cursor[i] = run;
        run += cnt[i];
    }
    if (t == 0) off[N] = E;
}

__global__ void reorder_kernel(const int* __restrict__ src, const int* __restrict__ dst,
                               int* cursor, int* srcs, int E) {
    int i = blockIdx.x * blockDim.x + threadIdx.x;
    if (i < E) {
        int d = dst[i];
        int p = atomicAdd(&cursor[d], 1);
        srcs[p] = src[i];
    }
}

// ---------------------------------------------------------------------------
// GEMM: C[r,:] = (A[r,:] @ B) * dinv[r];  B is Kx64.
// BM=128, BK=32, 256 threads, 8x4 microtile, vectorized LDS.
// ---------------------------------------------------------------------------
template <int K>
__launch_bounds__(256)
__global__ void gemm_scaled_kernel(const float* __restrict__ A, const float* __restrict__ B,
                                   const float* __restrict__ dinv, float* __restrict__ C,
                                   int M) {
    constexpr int BM = 128, BK = 32;
    __shared__ float As[BK][BM + 4];  // pad 4 to break stride-128 bank conflicts
    __shared__ float Bs[BK][64];

    const int tid = threadIdx.x;
    const int block_row = blockIdx.x * BM;
    const int tcol = (tid & 15) * 4;   // 0..60
    const int trow = (tid >> 4) * 4;   // 0..60 (second half at +64)

    float acc[8][4] = {};

    for (int k0 = 0; k0 < K; k0 += BK) {
        // A tile: 128x32 = 1024 float4, 4 per thread (stored transposed)
#pragma unroll
        for (int i = 0; i < 4; i++) {
            int idx = tid + i * 256;
            int r = idx >> 3;
            int c4 = (idx & 7) * 4;
            int grow = block_row + r;
            float4 v = make_float4(0.f, 0.f, 0.f, 0.f);
            if (grow < M)
                v = *reinterpret_cast<const float4*>(&A[(size_t)grow * K + k0 + c4]);
            As[c4 + 0][r] = v.x; As[c4 + 1][r] = v.y;
            As[c4 + 2][r] = v.z; As[c4 + 3][r] = v.w;
        }
        // B tile: 32x64 = 512 float4, 2 per thread
#pragma unroll
        for (int i = 0; i < 2; i++) {
            int idx = tid + i * 256;
            int r = idx >> 4;
            int c4 = (idx & 15) * 4;
            *reinterpret_cast<float4*>(&Bs[r][c4]) =
                *reinterpret_cast<const float4*>(&B[(size_t)(k0 + r) * 64 + c4]);
        }
        __syncthreads();

#pragma unroll
        for (int k = 0; k < BK; k++) {
            float4 a0 = *reinterpret_cast<const float4*>(&As[k][trow]);
            float4 a1 = *reinterpret_cast<const float4*>(&As[k][trow + 64]);
            float4 b  = *reinterpret_cast<const float4*>(&Bs[k][tcol]);
            const float am[8] = {a0.x, a0.y, a0.z, a0.w, a1.x, a1.y, a1.z, a1.w};
            const float bn[4] = {b.x, b.y, b.z, b.w};
#pragma unroll
            for (int i = 0; i < 8; i++)
#pragma unroll
                for (int j = 0; j < 4; j++) acc[i][j] = fmaf(am[i], bn[j], acc[i][j]);
        }
        __syncthreads();
    }

#pragma unroll
    for (int i = 0; i < 8; i++) {
        int rloc = (i < 4) ? (trow + i) : (trow + 60 + i);  // trow+64+(i-4)
        int grow = block_row + rloc;
        if (grow < M) {
            float s = dinv[grow];
            float4 v = make_float4(acc[i][0] * s, acc[i][1] * s, acc[i][2] * s, acc[i][3] * s);
            *reinterpret_cast<float4*>(&C[(size_t)grow * 64 + tcol]) = v;
        }
    }
}

// ---------------------------------------------------------------------------
// Gather-reduce per node: out[d] = dinv[d]*(h'[d] + sum_{e->d} h'[src_e]) + bias
// 16 threads per node, float4 per thread, unroll-4 for MLP.
// ---------------------------------------------------------------------------
template <bool RELU>
__global__ void gather_kernel(const float4* __restrict__ hs, const int* __restrict__ off,
                              const int* __restrict__ srcs, const float* __restrict__ dinv,
                              const float* __restrict__ bias, float4* __restrict__ out,
                              int N) {
    int i = blockIdx.x * blockDim.x + threadIdx.x;
    if (i >= N * 16) return;
    int node = i >> 4;
    int lane = i & 15;

    float4 acc = hs[(size_t)node * 16 + lane];  // self-loop term h'[d]
    int e = off[node];
    const int end = off[node + 1];

    for (; e + 4 <= end; e += 4) {
        int s0 = srcs[e], s1 = srcs[e + 1], s2 = srcs[e + 2], s3 = srcs[e + 3];
        float4 v0 = hs[(size_t)s0 * 16 + lane];
        float4 v1 = hs[(size_t)s1 * 16 + lane];
        float4 v2 = hs[(size_t)s2 * 16 + lane];
        float4 v3 = hs[(size_t)s3 * 16 + lane];
        acc.x += (v0.x + v1.x) + (v2.x + v3.x);
        acc.y += (v0.y + v1.y) + (v2.y + v3.y);
        acc.z += (v0.z + v1.z) + (v2.z + v3.z);
        acc.w += (v0.w + v1.w) + (v2.w + v3.w);
    }
    for (; e < end; e++) {
        int s = srcs[e];
        float4 v = hs[(size_t)s * 16 + lane];
        acc.x += v.x; acc.y += v.y; acc.z += v.z; acc.w += v.w;
    }

    float dd = dinv[node];
    float4 bv = reinterpret_cast<const float4*>(bias)[lane];
    float r0 = fmaf(acc.x, dd, bv.x);
    float r1 = fmaf(acc.y, dd, bv.y);
    float r2 = fmaf(acc.z, dd, bv.z);
    float r3 = fmaf(acc.w, dd, bv.w);
    if (RELU) {
        r0 = fmaxf(r0, 0.f); r1 = fmaxf(r1, 0.f);
        r2 = fmaxf(r2, 0.f); r3 = fmaxf(r3, 0.f);
    }
    out[(size_t)node * 16 + lane] = make_float4(r0, r1, r2, r3);
}

// ---------------------------------------------------------------------------
// launch
// ---------------------------------------------------------------------------
extern "C" void kernel_launch(void* const* d_in, const int* in_sizes, int n_in,
                              void* d_out, int out_size) {
    const float* x = (const float*)d_in[0];
    const int* edge_index = (const int*)d_in[1];
    const float* W1 = (const float*)d_in[2];
    const float* b1 = (const float*)d_in[3];
    const float* W2 = (const float*)d_in[4];
    const float* b2 = (const float*)d_in[5];
    float* out = (float*)d_out;

    const int IN_CH = 256;
    const int N = in_sizes[0] / IN_CH;  // 100000
    const int E = in_sizes[1] / 2;      // 3200000
    const int* src = edge_index;
    const int* dst = edge_index + E;

    int *cnt, *off, *cursor, *srcs;
    float *dinv, *h1, *hid, *h2;
    cudaGetSymbolAddress((void**)&cnt, g_cnt);
    cudaGetSymbolAddress((void**)&off, g_off);
    cudaGetSymbolAddress((void**)&cursor, g_cursor);
    cudaGetSymbolAddress((void**)&srcs, g_srcs);
    cudaGetSymbolAddress((void**)&dinv, g_dinv);
    cudaGetSymbolAddress((void**)&h1, g_h1);
    cudaGetSymbolAddress((void**)&hid, g_hid);
    cudaGetSymbolAddress((void**)&h2, g_h2);

    const int T = 256;
    int nBlkN = (N + T - 1) / T;
    int nBlkE = (E + T - 1) / T;
    int nBlkG = (N + 127) / 128;
    int nBlkGa = (N * 16 + T - 1) / T;

    // CSR build
    zero_cnt_kernel<<<nBlkN, T>>>(cnt, N);
    hist_kernel<<<nBlkE, T>>>(dst, cnt, E);
    dinv_kernel<<<nBlkN, T>>>(cnt, dinv, N);
    scan_kernel<<<1, 1024>>>(cnt, off, cursor, N, E);
    reorder_kernel<<<nBlkE, T>>>(src, dst, cursor, srcs, E);

    // layer 1
    gemm_scaled_kernel<256><<<nBlkG, T>>>(x, W1, dinv, h1, N);
    gather_kernel<true><<<nBlkGa, T>>>((const float4*)h1, off, srcs, dinv, b1, (float4*)hid, N);

    // layer 2
    gemm_scaled_kernel<64><<<nBlkG, T>>>(hid, W2, dinv, h2, N);
    gather_kernel<false><<<nBlkGa, T>>>((const float4*)h2, off, srcs, dinv, b2, (float4*)out, N);
}

// round 4
// speedup vs baseline: 2.0079x; 1.5538x over previous
#include <cuda_runtime.h>
#include <cuda_bf16.h>
#include <cstdint>

#define MAX_NODES 100000
#define MAX_EDGES 3200000
#define HID 64

// Scratch (__device__ globals; 16B aligned for float4)
__device__ __align__(16) int   g_cnt[MAX_NODES];
__device__ __align__(16) int   g_off[MAX_NODES];
__device__ __align__(16) int   g_cursor[MAX_NODES];
__device__ __align__(16) int   g_srcs[MAX_EDGES];
__device__                int  g_total;
__device__ __align__(16) float g_dinv[MAX_NODES];
__device__ __align__(16) float g_h1[MAX_NODES * HID];   // h1' = (x@W1)*dinv
__device__ __align__(16) float g_hid[MAX_NODES * HID];  // relu'd hidden
__device__ __align__(16) float g_h2[MAX_NODES * HID];   // h2' = (hid@W2)*dinv

// ---------------------------------------------------------------------------
// CSR construction: histogram -> decoupled offsets -> reorder
// ---------------------------------------------------------------------------
__global__ void zero_cnt_kernel(int* cnt, int* total, int N) {
    int i = blockIdx.x * blockDim.x + threadIdx.x;
    if (i < N) cnt[i] = 0;
    if (i == 0) *total = 0;
}

__global__ void hist_kernel(const int* __restrict__ dst, int* cnt, int E) {
    int i = blockIdx.x * blockDim.x + threadIdx.x;
    if (i < E) atomicAdd(&cnt[dst[i]], 1);
}

__global__ void dinv_kernel(const int* __restrict__ cnt, float* dinv, int N) {
    int i = blockIdx.x * blockDim.x + threadIdx.x;
    if (i < N) dinv[i] = rsqrtf((float)cnt[i] + 1.0f);  // +1 self-loop
}

// Per-block scan + one atomicAdd per block for the base. Segment order across
// blocks is arbitrary (atomic arrival order) — gather only needs contiguity.
__launch_bounds__(256)
__global__ void offsets_kernel(const int* __restrict__ cnt, int* off, int* cursor,
                               int* total, int N) {
    const int tid = threadIdx.x;
    const int i = blockIdx.x * 256 + tid;
    const int lane = tid & 31;
    const int warp = tid >> 5;

    int c = (i < N) ? cnt[i] : 0;

    // warp inclusive scan
    int incl = c;
#pragma unroll
    for (int d = 1; d < 32; d <<= 1) {
        int v = __shfl_up_sync(0xFFFFFFFFu, incl, d);
        if (lane >= d) incl += v;
    }

    __shared__ int wsum[8];
    __shared__ int base;
    if (lane == 31) wsum[warp] = incl;
    __syncthreads();
    if (warp == 0) {
        int w = (lane < 8) ? wsum[lane] : 0;
#pragma unroll
        for (int d = 1; d < 8; d <<= 1) {
            int v = __shfl_up_sync(0xFFFFFFFFu, w, d);
            if (lane >= d) w += v;
        }
        if (lane < 8) wsum[lane] = w;
    }
    __syncthreads();
    int inclTotal = incl + ((warp > 0) ? wsum[warp - 1] : 0);
    if (tid == 255) base = atomicAdd(total, inclTotal);  // block total
    __syncthreads();
    if (i < N) {
        int o = base + inclTotal - c;  // exclusive offset
        off[i] = o;
        cursor[i] = o;
    }
}

__global__ void reorder_kernel(const int* __restrict__ src, const int* __restrict__ dst,
                               int* cursor, int* srcs, int E) {
    int i = blockIdx.x * blockDim.x + threadIdx.x;
    if (i < E) {
        int d = dst[i];
        int p = atomicAdd(&cursor[d], 1);
        srcs[p] = src[i];
    }
}

// ---------------------------------------------------------------------------
// GEMM: C[r,:] = (A[r,:] @ B) * dinv[r];  B is Kx64.
// BM=128, BK=32, 256 threads, 8x4 microtile, vectorized LDS.
// ---------------------------------------------------------------------------
template <int K>
__launch_bounds__(256)
__global__ void gemm_scaled_kernel(const float* __restrict__ A, const float* __restrict__ B,
                                   const float* __restrict__ dinv, float* __restrict__ C,
                                   int M) {
    constexpr int BM = 128, BK = 32;
    __shared__ float As[BK][BM + 4];
    __shared__ float Bs[BK][64];

    const int tid = threadIdx.x;
    const int block_row = blockIdx.x * BM;
    const int tcol = (tid & 15) * 4;
    const int trow = (tid >> 4) * 4;

    float acc[8][4] = {};

    for (int k0 = 0; k0 < K; k0 += BK) {
#pragma unroll
        for (int i = 0; i < 4; i++) {
            int idx = tid + i * 256;
            int r = idx >> 3;
            int c4 = (idx & 7) * 4;
            int grow = block_row + r;
            float4 v = make_float4(0.f, 0.f, 0.f, 0.f);
            if (grow < M)
                v = *reinterpret_cast<const float4*>(&A[(size_t)grow * K + k0 + c4]);
            As[c4 + 0][r] = v.x; As[c4 + 1][r] = v.y;
            As[c4 + 2][r] = v.z; As[c4 + 3][r] = v.w;
        }
#pragma unroll
        for (int i = 0; i < 2; i++) {
            int idx = tid + i * 256;
            int r = idx >> 4;
            int c4 = (idx & 15) * 4;
            *reinterpret_cast<float4*>(&Bs[r][c4]) =
                *reinterpret_cast<const float4*>(&B[(size_t)(k0 + r) * 64 + c4]);
        }
        __syncthreads();

#pragma unroll
        for (int k = 0; k < BK; k++) {
            float4 a0 = *reinterpret_cast<const float4*>(&As[k][trow]);
            float4 a1 = *reinterpret_cast<const float4*>(&As[k][trow + 64]);
            float4 b  = *reinterpret_cast<const float4*>(&Bs[k][tcol]);
            const float am[8] = {a0.x, a0.y, a0.z, a0.w, a1.x, a1.y, a1.z, a1.w};
            const float bn[4] = {b.x, b.y, b.z, b.w};
#pragma unroll
            for (int i = 0; i < 8; i++)
#pragma unroll
                for (int j = 0; j < 4; j++) acc[i][j] = fmaf(am[i], bn[j], acc[i][j]);
        }
        __syncthreads();
    }

#pragma unroll
    for (int i = 0; i < 8; i++) {
        int rloc = (i < 4) ? (trow + i) : (trow + 60 + i);
        int grow = block_row + rloc;
        if (grow < M) {
            float s = dinv[grow];
            float4 v = make_float4(acc[i][0] * s, acc[i][1] * s, acc[i][2] * s, acc[i][3] * s);
            *reinterpret_cast<float4*>(&C[(size_t)grow * 64 + tcol]) = v;
        }
    }
}

// ---------------------------------------------------------------------------
// Gather-reduce: out[d] = dinv[d]*(h'[d] + sum_{e->d} h'[src_e]) + bias
// 16 threads per node, float4 per thread, unroll-4.
// ---------------------------------------------------------------------------
template <bool RELU>
__global__ void gather_kernel(const float4* __restrict__ hs, const int* __restrict__ off,
                              const int* __restrict__ cnt, const int* __restrict__ srcs,
                              const float* __restrict__ dinv, const float* __restrict__ bias,
                              float4* __restrict__ out, int N) {
    int i = blockIdx.x * blockDim.x + threadIdx.x;
    if (i >= N * 16) return;
    int node = i >> 4;
    int lane = i & 15;

    float4 acc = hs[(size_t)node * 16 + lane];  // self-loop term
    int e = off[node];
    const int end = e + cnt[node];

    for (; e + 4 <= end; e += 4) {
        int s0 = srcs[e], s1 = srcs[e + 1], s2 = srcs[e + 2], s3 = srcs[e + 3];
        float4 v0 = hs[(size_t)s0 * 16 + lane];
        float4 v1 = hs[(size_t)s1 * 16 + lane];
        float4 v2 = hs[(size_t)s2 * 16 + lane];
        float4 v3 = hs[(size_t)s3 * 16 + lane];
        acc.x += (v0.x + v1.x) + (v2.x + v3.x);
        acc.y += (v0.y + v1.y) + (v2.y + v3.y);
        acc.z += (v0.z + v1.z) + (v2.z + v3.z);
        acc.w += (v0.w + v1.w) + (v2.w + v3.w);
    }
    for (; e < end; e++) {
        int s = srcs[e];
        float4 v = hs[(size_t)s * 16 + lane];
        acc.x += v.x; acc.y += v.y; acc.z += v.z; acc.w += v.w;
    }

    float dd = dinv[node];
    float4 bv = reinterpret_cast<const float4*>(bias)[lane];
    float r0 = fmaf(acc.x, dd, bv.x);
    float r1 = fmaf(acc.y, dd, bv.y);
    float r2 = fmaf(acc.z, dd, bv.z);
    float r3 = fmaf(acc.w, dd, bv.w);
    if (RELU) {
        r0 = fmaxf(r0, 0.f); r1 = fmaxf(r1, 0.f);
        r2 = fmaxf(r2, 0.f); r3 = fmaxf(r3, 0.f);
    }
    out[(size_t)node * 16 + lane] = make_float4(r0, r1, r2, r3);
}

// ---------------------------------------------------------------------------
// launch
// ---------------------------------------------------------------------------
extern "C" void kernel_launch(void* const* d_in, const int* in_sizes, int n_in,
                              void* d_out, int out_size) {
    const float* x = (const float*)d_in[0];
    const int* edge_index = (const int*)d_in[1];
    const float* W1 = (const float*)d_in[2];
    const float* b1 = (const float*)d_in[3];
    const float* W2 = (const float*)d_in[4];
    const float* b2 = (const float*)d_in[5];
    float* out = (float*)d_out;

    const int IN_CH = 256;
    const int N = in_sizes[0] / IN_CH;  // 100000
    const int E = in_sizes[1] / 2;      // 3200000
    const int* src = edge_index;
    const int* dst = edge_index + E;

    int *cnt, *off, *cursor, *srcs, *total;
    float *dinv, *h1, *hid, *h2;
    cudaGetSymbolAddress((void**)&cnt, g_cnt);
    cudaGetSymbolAddress((void**)&off, g_off);
    cudaGetSymbolAddress((void**)&cursor, g_cursor);
    cudaGetSymbolAddress((void**)&srcs, g_srcs);
    cudaGetSymbolAddress((void**)&total, g_total);
    cudaGetSymbolAddress((void**)&dinv, g_dinv);
    cudaGetSymbolAddress((void**)&h1, g_h1);
    cudaGetSymbolAddress((void**)&hid, g_hid);
    cudaGetSymbolAddress((void**)&h2, g_h2);

    const int T = 256;
    int nBlkN = (N + T - 1) / T;
    int nBlkE = (E + T - 1) / T;
    int nBlkG = (N + 127) / 128;
    int nBlkGa = (N * 16 + T - 1) / T;

    // CSR build
    zero_cnt_kernel<<<nBlkN, T>>>(cnt, total, N);
    hist_kernel<<<nBlkE, T>>>(dst, cnt, E);
    dinv_kernel<<<nBlkN, T>>>(cnt, dinv, N);
    offsets_kernel<<<nBlkN, T>>>(cnt, off, cursor, total, N);
    reorder_kernel<<<nBlkE, T>>>(src, dst, cursor, srcs, E);

    // layer 1
    gemm_scaled_kernel<256><<<nBlkG, T>>>(x, W1, dinv, h1, N);
    gather_kernel<true><<<nBlkGa, T>>>((const float4*)h1, off, cnt, srcs, dinv, b1, (float4*)hid, N);

    // layer 2
    gemm_scaled_kernel<64><<<nBlkG, T>>>(hid, W2, dinv, h2, N);
    gather_kernel<false><<<nBlkGa, T>>>((const float4*)h2, off, cnt, srcs, dinv, b2, (float4*)out, N);
}

// round 5
// speedup vs baseline: 2.1492x; 1.0704x over previous
#include <cuda_runtime.h>
#include <cuda_fp16.h>
#include <cstdint>

#define MAX_NODES 100000
#define MAX_EDGES 3200000
#define HID 64

// Scratch (__device__ globals; 16B aligned)
__device__ __align__(16) int    g_cnt[MAX_NODES];
__device__ __align__(16) int    g_off[MAX_NODES];
__device__ __align__(16) int    g_cursor[MAX_NODES];
__device__ __align__(16) int    g_srcs[MAX_EDGES];
__device__                int   g_total;
__device__ __align__(16) float  g_dinv[MAX_NODES];
__device__ __align__(16) __half g_h1[MAX_NODES * HID];   // h1' = (x@W1)*dinv, fp16
__device__ __align__(16) float  g_hid[MAX_NODES * HID];  // relu'd hidden (fp32, GEMM2 A)
__device__ __align__(16) __half g_h2[MAX_NODES * HID];   // h2' = (hid@W2)*dinv, fp16

// ---------------------------------------------------------------------------
// CSR construction: histogram -> decoupled offsets -> reorder
// ---------------------------------------------------------------------------
__global__ void zero_cnt_kernel(int* cnt, int* total, int N) {
    int i = blockIdx.x * blockDim.x + threadIdx.x;
    if (i < N) cnt[i] = 0;
    if (i == 0) *total = 0;
}

__global__ void hist_kernel(const int* __restrict__ dst, int* cnt, int E) {
    int i = blockIdx.x * blockDim.x + threadIdx.x;
    if (i < E) atomicAdd(&cnt[dst[i]], 1);
}

__global__ void dinv_kernel(const int* __restrict__ cnt, float* dinv, int N) {
    int i = blockIdx.x * blockDim.x + threadIdx.x;
    if (i < N) dinv[i] = rsqrtf((float)cnt[i] + 1.0f);  // +1 self-loop
}

// Per-block scan + one atomicAdd per block for the base (segment order arbitrary).
__launch_bounds__(256)
__global__ void offsets_kernel(const int* __restrict__ cnt, int* off, int* cursor,
                               int* total, int N) {
    const int tid = threadIdx.x;
    const int i = blockIdx.x * 256 + tid;
    const int lane = tid & 31;
    const int warp = tid >> 5;

    int c = (i < N) ? cnt[i] : 0;

    int incl = c;
#pragma unroll
    for (int d = 1; d < 32; d <<= 1) {
        int v = __shfl_up_sync(0xFFFFFFFFu, incl, d);
        if (lane >= d) incl += v;
    }

    __shared__ int wsum[8];
    __shared__ int base;
    if (lane == 31) wsum[warp] = incl;
    __syncthreads();
    if (warp == 0) {
        int w = (lane < 8) ? wsum[lane] : 0;
#pragma unroll
        for (int d = 1; d < 8; d <<= 1) {
            int v = __shfl_up_sync(0xFFFFFFFFu, w, d);
            if (lane >= d) w += v;
        }
        if (lane < 8) wsum[lane] = w;
    }
    __syncthreads();
    int inclTotal = incl + ((warp > 0) ? wsum[warp - 1] : 0);
    if (tid == 255) base = atomicAdd(total, inclTotal);
    __syncthreads();
    if (i < N) {
        int o = base + inclTotal - c;
        off[i] = o;
        cursor[i] = o;
    }
}

__global__ void reorder_kernel(const int* __restrict__ src, const int* __restrict__ dst,
                               int* cursor, int* srcs, int E) {
    int i = blockIdx.x * blockDim.x + threadIdx.x;
    if (i < E) {
        int d = dst[i];
        int p = atomicAdd(&cursor[d], 1);
        srcs[p] = src[i];
    }
}

// ---------------------------------------------------------------------------
// GEMM: C[r,:] = half( (A[r,:] @ B) * dinv[r] );  B is Kx64, C is fp16.
// BM=128, BK=32, 256 threads, 8x4 microtile.
// ---------------------------------------------------------------------------
template <int K>
__launch_bounds__(256)
__global__ void gemm_scaled_h_kernel(const float* __restrict__ A, const float* __restrict__ B,
                                     const float* __restrict__ dinv, __half* __restrict__ C,
                                     int M) {
    constexpr int BM = 128, BK = 32;
    __shared__ float As[BK][BM + 4];
    __shared__ float Bs[BK][64];

    const int tid = threadIdx.x;
    const int block_row = blockIdx.x * BM;
    const int tcol = (tid & 15) * 4;
    const int trow = (tid >> 4) * 4;

    float acc[8][4] = {};

    for (int k0 = 0; k0 < K; k0 += BK) {
#pragma unroll
        for (int i = 0; i < 4; i++) {
            int idx = tid + i * 256;
            int r = idx >> 3;
            int c4 = (idx & 7) * 4;
            int grow = block_row + r;
            float4 v = make_float4(0.f, 0.f, 0.f, 0.f);
            if (grow < M)
                v = *reinterpret_cast<const float4*>(&A[(size_t)grow * K + k0 + c4]);
            As[c4 + 0][r] = v.x; As[c4 + 1][r] = v.y;
            As[c4 + 2][r] = v.z; As[c4 + 3][r] = v.w;
        }
#pragma unroll
        for (int i = 0; i < 2; i++) {
            int idx = tid + i * 256;
            int r = idx >> 4;
            int c4 = (idx & 15) * 4;
            *reinterpret_cast<float4*>(&Bs[r][c4]) =
                *reinterpret_cast<const float4*>(&B[(size_t)(k0 + r) * 64 + c4]);
        }
        __syncthreads();

#pragma unroll
        for (int k = 0; k < BK; k++) {
            float4 a0 = *reinterpret_cast<const float4*>(&As[k][trow]);
            float4 a1 = *reinterpret_cast<const float4*>(&As[k][trow + 64]);
            float4 b  = *reinterpret_cast<const float4*>(&Bs[k][tcol]);
            const float am[8] = {a0.x, a0.y, a0.z, a0.w, a1.x, a1.y, a1.z, a1.w};
            const float bn[4] = {b.x, b.y, b.z, b.w};
#pragma unroll
            for (int i = 0; i < 8; i++)
#pragma unroll
                for (int j = 0; j < 4; j++) acc[i][j] = fmaf(am[i], bn[j], acc[i][j]);
        }
        __syncthreads();
    }

#pragma unroll
    for (int i = 0; i < 8; i++) {
        int rloc = (i < 4) ? (trow + i) : (trow + 60 + i);
        int grow = block_row + rloc;
        if (grow < M) {
            float s = dinv[grow];
            __half2 p0 = __floats2half2_rn(acc[i][0] * s, acc[i][1] * s);
            __half2 p1 = __floats2half2_rn(acc[i][2] * s, acc[i][3] * s);
            uint2 u;
            u.x = *reinterpret_cast<const unsigned*>(&p0);
            u.y = *reinterpret_cast<const unsigned*>(&p1);
            *reinterpret_cast<uint2*>(&C[(size_t)grow * 64 + tcol]) = u;
        }
    }
}

// ---------------------------------------------------------------------------
// Gather-reduce (fp16 table): out[d] = dinv[d]*(h'[d] + sum h'[src]) + bias
// 16 threads/node; each lane owns 4 channels via one uint2 (4 halves) per row.
// ---------------------------------------------------------------------------
__device__ __forceinline__ void acc_half4(float4& acc, uint2 u) {
    __half2 h0 = *reinterpret_cast<const __half2*>(&u.x);
    __half2 h1 = *reinterpret_cast<const __half2*>(&u.y);
    float2 f0 = __half22float2(h0);
    float2 f1 = __half22float2(h1);
    acc.x += f0.x; acc.y += f0.y; acc.z += f1.x; acc.w += f1.y;
}

template <bool RELU>
__global__ void gather_kernel(const uint2* __restrict__ hs, const int* __restrict__ off,
                              const int* __restrict__ cnt, const int* __restrict__ srcs,
                              const float* __restrict__ dinv, const float* __restrict__ bias,
                              float4* __restrict__ out, int N) {
    int i = blockIdx.x * blockDim.x + threadIdx.x;
    if (i >= N * 16) return;
    int node = i >> 4;
    int lane = i & 15;

    float4 acc = make_float4(0.f, 0.f, 0.f, 0.f);
    acc_half4(acc, hs[(size_t)node * 16 + lane]);  // self-loop term
    int e = off[node];
    const int end = e + cnt[node];

    for (; e + 4 <= end; e += 4) {
        int s0 = srcs[e], s1 = srcs[e + 1], s2 = srcs[e + 2], s3 = srcs[e + 3];
        uint2 v0 = hs[(size_t)s0 * 16 + lane];
        uint2 v1 = hs[(size_t)s1 * 16 + lane];
        uint2 v2 = hs[(size_t)s2 * 16 + lane];
        uint2 v3 = hs[(size_t)s3 * 16 + lane];
        acc_half4(acc, v0); acc_half4(acc, v1);
        acc_half4(acc, v2); acc_half4(acc, v3);
    }
    for (; e < end; e++) {
        acc_half4(acc, hs[(size_t)srcs[e] * 16 + lane]);
    }

    float dd = dinv[node];
    float4 bv = reinterpret_cast<const float4*>(bias)[lane];
    float r0 = fmaf(acc.x, dd, bv.x);
    float r1 = fmaf(acc.y, dd, bv.y);
    float r2 = fmaf(acc.z, dd, bv.z);
    float r3 = fmaf(acc.w, dd, bv.w);
    if (RELU) {
        r0 = fmaxf(r0, 0.f); r1 = fmaxf(r1, 0.f);
        r2 = fmaxf(r2, 0.f); r3 = fmaxf(r3, 0.f);
    }
    out[(size_t)node * 16 + lane] = make_float4(r0, r1, r2, r3);
}

// ---------------------------------------------------------------------------
// launch
// ---------------------------------------------------------------------------
extern "C" void kernel_launch(void* const* d_in, const int* in_sizes, int n_in,
                              void* d_out, int out_size) {
    const float* x = (const float*)d_in[0];
    const int* edge_index = (const int*)d_in[1];
    const float* W1 = (const float*)d_in[2];
    const float* b1 = (const float*)d_in[3];
    const float* W2 = (const float*)d_in[4];
    const float* b2 = (const float*)d_in[5];
    float* out = (float*)d_out;

    const int IN_CH = 256;
    const int N = in_sizes[0] / IN_CH;  // 100000
    const int E = in_sizes[1] / 2;      // 3200000
    const int* src = edge_index;
    const int* dst = edge_index + E;

    int *cnt, *off, *cursor, *srcs, *total;
    float *dinv, *hid;
    __half *h1, *h2;
    cudaGetSymbolAddress((void**)&cnt, g_cnt);
    cudaGetSymbolAddress((void**)&off, g_off);
    cudaGetSymbolAddress((void**)&cursor, g_cursor);
    cudaGetSymbolAddress((void**)&srcs, g_srcs);
    cudaGetSymbolAddress((void**)&total, g_total);
    cudaGetSymbolAddress((void**)&dinv, g_dinv);
    cudaGetSymbolAddress((void**)&h1, g_h1);
    cudaGetSymbolAddress((void**)&hid, g_hid);
    cudaGetSymbolAddress((void**)&h2, g_h2);

    const int T = 256;
    int nBlkN = (N + T - 1) / T;
    int nBlkE = (E + T - 1) / T;
    int nBlkG = (N + 127) / 128;
    int nBlkGa = (N * 16 + T - 1) / T;

    // CSR build
    zero_cnt_kernel<<<nBlkN, T>>>(cnt, total, N);
    hist_kernel<<<nBlkE, T>>>(dst, cnt, E);
    dinv_kernel<<<nBlkN, T>>>(cnt, dinv, N);
    offsets_kernel<<<nBlkN, T>>>(cnt, off, cursor, total, N);
    reorder_kernel<<<nBlkE, T>>>(src, dst, cursor, srcs, E);

    // layer 1
    gemm_scaled_h_kernel<256><<<nBlkG, T>>>(x, W1, dinv, h1, N);
    gather_kernel<true><<<nBlkGa, T>>>((const uint2*)h1, off, cnt, srcs, dinv, b1,
                                       (float4*)hid, N);

    // layer 2
    gemm_scaled_h_kernel<64><<<nBlkG, T>>>(hid, W2, dinv, h2, N);
    gather_kernel<false><<<nBlkGa, T>>>((const uint2*)h2, off, cnt, srcs, dinv, b2,
                                        (float4*)out, N);
}

// round 6
// speedup vs baseline: 2.1559x; 1.0031x over previous
#include <cuda_runtime.h>
#include <cuda_fp16.h>
#include <cstdint>

#define MAX_NODES 100000
#define MAX_EDGES 3200000
#define HID 64

// Scratch (__device__ globals; 16B aligned)
__device__ __align__(16) int    g_cnt[MAX_NODES];
__device__ __align__(16) int    g_off[MAX_NODES];
__device__ __align__(16) int    g_cursor[MAX_NODES];
__device__ __align__(16) int    g_srcs[MAX_EDGES];
__device__                int   g_total;
__device__ __align__(16) float  g_dinv[MAX_NODES];
__device__ __align__(16) __half g_h1[MAX_NODES * HID];   // h1' = (x@W1)*dinv, fp16
__device__ __align__(16) float  g_hid[MAX_NODES * HID];  // relu'd hidden (fp32, GEMM2 A)
__device__ __align__(16) __half g_h2[MAX_NODES * HID];   // h2' = (hid@W2)*dinv, fp16

// ---------------------------------------------------------------------------
// CSR construction: histogram -> decoupled offsets -> reorder
// ---------------------------------------------------------------------------
__global__ void zero_cnt_kernel(int* cnt, int* total, int N) {
    int i = blockIdx.x * blockDim.x + threadIdx.x;
    if (i < N) cnt[i] = 0;
    if (i == 0) *total = 0;
}

__global__ void hist_kernel(const int* __restrict__ dst, int* cnt, int E) {
    int i = blockIdx.x * blockDim.x + threadIdx.x;
    if (i < E) atomicAdd(&cnt[dst[i]], 1);
}

__global__ void dinv_kernel(const int* __restrict__ cnt, float* dinv, int N) {
    int i = blockIdx.x * blockDim.x + threadIdx.x;
    if (i < N) dinv[i] = rsqrtf((float)cnt[i] + 1.0f);  // +1 self-loop
}

// Per-block scan + one atomicAdd per block for the base (segment order arbitrary).
__launch_bounds__(256)
__global__ void offsets_kernel(const int* __restrict__ cnt, int* off, int* cursor,
                               int* total, int N) {
    const int tid = threadIdx.x;
    const int i = blockIdx.x * 256 + tid;
    const int lane = tid & 31;
    const int warp = tid >> 5;

    int c = (i < N) ? cnt[i] : 0;

    int incl = c;
#pragma unroll
    for (int d = 1; d < 32; d <<= 1) {
        int v = __shfl_up_sync(0xFFFFFFFFu, incl, d);
        if (lane >= d) incl += v;
    }

    __shared__ int wsum[8];
    __shared__ int base;
    if (lane == 31) wsum[warp] = incl;
    __syncthreads();
    if (warp == 0) {
        int w = (lane < 8) ? wsum[lane] : 0;
#pragma unroll
        for (int d = 1; d < 8; d <<= 1) {
            int v = __shfl_up_sync(0xFFFFFFFFu, w, d);
            if (lane >= d) w += v;
        }
        if (lane < 8) wsum[lane] = w;
    }
    __syncthreads();
    int inclTotal = incl + ((warp > 0) ? wsum[warp - 1] : 0);
    if (tid == 255) base = atomicAdd(total, inclTotal);
    __syncthreads();
    if (i < N) {
        int o = base + inclTotal - c;
        off[i] = o;
        cursor[i] = o;
    }
}

__global__ void reorder_kernel(const int* __restrict__ src, const int* __restrict__ dst,
                               int* cursor, int* srcs, int E) {
    int i = blockIdx.x * blockDim.x + threadIdx.x;
    if (i < E) {
        int d = dst[i];
        int p = atomicAdd(&cursor[d], 1);
        srcs[p] = src[i];
    }
}

// ---------------------------------------------------------------------------
// GEMM: C[r,:] = half( (A[r,:] @ B) * dinv[r] );  B is Kx64, C is fp16.
// BM=128, BK=32, 256 threads, 8x4 microtile.
// ---------------------------------------------------------------------------
template <int K>
__launch_bounds__(256)
__global__ void gemm_scaled_h_kernel(const float* __restrict__ A, const float* __restrict__ B,
                                     const float* __restrict__ dinv, __half* __restrict__ C,
                                     int M) {
    constexpr int BM = 128, BK = 32;
    __shared__ float As[BK][BM + 4];
    __shared__ float Bs[BK][64];

    const int tid = threadIdx.x;
    const int block_row = blockIdx.x * BM;
    const int tcol = (tid & 15) * 4;
    const int trow = (tid >> 4) * 4;

    float acc[8][4] = {};

    for (int k0 = 0; k0 < K; k0 += BK) {
#pragma unroll
        for (int i = 0; i < 4; i++) {
            int idx = tid + i * 256;
            int r = idx >> 3;
            int c4 = (idx & 7) * 4;
            int grow = block_row + r;
            float4 v = make_float4(0.f, 0.f, 0.f, 0.f);
            if (grow < M)
                v = *reinterpret_cast<const float4*>(&A[(size_t)grow * K + k0 + c4]);
            As[c4 + 0][r] = v.x; As[c4 + 1][r] = v.y;
            As[c4 + 2][r] = v.z; As[c4 + 3][r] = v.w;
        }
#pragma unroll
        for (int i = 0; i < 2; i++) {
            int idx = tid + i * 256;
            int r = idx >> 4;
            int c4 = (idx & 15) * 4;
            *reinterpret_cast<float4*>(&Bs[r][c4]) =
                *reinterpret_cast<const float4*>(&B[(size_t)(k0 + r) * 64 + c4]);
        }
        __syncthreads();

#pragma unroll
        for (int k = 0; k < BK; k++) {
            float4 a0 = *reinterpret_cast<const float4*>(&As[k][trow]);
            float4 a1 = *reinterpret_cast<const float4*>(&As[k][trow + 64]);
            float4 b  = *reinterpret_cast<const float4*>(&Bs[k][tcol]);
            const float am[8] = {a0.x, a0.y, a0.z, a0.w, a1.x, a1.y, a1.z, a1.w};
            const float bn[4] = {b.x, b.y, b.z, b.w};
#pragma unroll
            for (int i = 0; i < 8; i++)
#pragma unroll
                for (int j = 0; j < 4; j++) acc[i][j] = fmaf(am[i], bn[j], acc[i][j]);
        }
        __syncthreads();
    }

#pragma unroll
    for (int i = 0; i < 8; i++) {
        int rloc = (i < 4) ? (trow + i) : (trow + 60 + i);
        int grow = block_row + rloc;
        if (grow < M) {
            float s = dinv[grow];
            __half2 p0 = __floats2half2_rn(acc[i][0] * s, acc[i][1] * s);
            __half2 p1 = __floats2half2_rn(acc[i][2] * s, acc[i][3] * s);
            uint2 u;
            u.x = *reinterpret_cast<const unsigned*>(&p0);
            u.y = *reinterpret_cast<const unsigned*>(&p1);
            *reinterpret_cast<uint2*>(&C[(size_t)grow * 64 + tcol]) = u;
        }
    }
}

// ---------------------------------------------------------------------------
// Gather-reduce (fp16 table): out[d] = dinv[d]*(h'[d] + sum h'[src]) + bias
// 16 threads/node; each lane owns 4 channels via one uint2 (4 halves) per row.
// ---------------------------------------------------------------------------
__device__ __forceinline__ void acc_half4(float4& acc, uint2 u) {
    __half2 h0 = *reinterpret_cast<const __half2*>(&u.x);
    __half2 h1 = *reinterpret_cast<const __half2*>(&u.y);
    float2 f0 = __half22float2(h0);
    float2 f1 = __half22float2(h1);
    acc.x += f0.x; acc.y += f0.y; acc.z += f1.x; acc.w += f1.y;
}

template <bool RELU>
__global__ void gather_kernel(const uint2* __restrict__ hs, const int* __restrict__ off,
                              const int* __restrict__ cnt, const int* __restrict__ srcs,
                              const float* __restrict__ dinv, const float* __restrict__ bias,
                              float4* __restrict__ out, int N) {
    int i = blockIdx.x * blockDim.x + threadIdx.x;
    if (i >= N * 16) return;
    int node = i >> 4;
    int lane = i & 15;

    float4 acc = make_float4(0.f, 0.f, 0.f, 0.f);
    acc_half4(acc, hs[(size_t)node * 16 + lane]);  // self-loop term
    int e = off[node];
    const int end = e + cnt[node];

    for (; e + 4 <= end; e += 4) {
        int s0 = srcs[e], s1 = srcs[e + 1], s2 = srcs[e + 2], s3 = srcs[e + 3];
        uint2 v0 = hs[(size_t)s0 * 16 + lane];
        uint2 v1 = hs[(size_t)s1 * 16 + lane];
        uint2 v2 = hs[(size_t)s2 * 16 + lane];
        uint2 v3 = hs[(size_t)s3 * 16 + lane];
        acc_half4(acc, v0); acc_half4(acc, v1);
        acc_half4(acc, v2); acc_half4(acc, v3);
    }
    for (; e < end; e++) {
        acc_half4(acc, hs[(size_t)srcs[e] * 16 + lane]);
    }

    float dd = dinv[node];
    float4 bv = reinterpret_cast<const float4*>(bias)[lane];
    float r0 = fmaf(acc.x, dd, bv.x);
    float r1 = fmaf(acc.y, dd, bv.y);
    float r2 = fmaf(acc.z, dd, bv.z);
    float r3 = fmaf(acc.w, dd, bv.w);
    if (RELU) {
        r0 = fmaxf(r0, 0.f); r1 = fmaxf(r1, 0.f);
        r2 = fmaxf(r2, 0.f); r3 = fmaxf(r3, 0.f);
    }
    out[(size_t)node * 16 + lane] = make_float4(r0, r1, r2, r3);
}

// ---------------------------------------------------------------------------
// launch
// ---------------------------------------------------------------------------
extern "C" void kernel_launch(void* const* d_in, const int* in_sizes, int n_in,
                              void* d_out, int out_size) {
    const float* x = (const float*)d_in[0];
    const int* edge_index = (const int*)d_in[1];
    const float* W1 = (const float*)d_in[2];
    const float* b1 = (const float*)d_in[3];
    const float* W2 = (const float*)d_in[4];
    const float* b2 = (const float*)d_in[5];
    float* out = (float*)d_out;

    const int IN_CH = 256;
    const int N = in_sizes[0] / IN_CH;  // 100000
    const int E = in_sizes[1] / 2;      // 3200000
    const int* src = edge_index;
    const int* dst = edge_index + E;

    int *cnt, *off, *cursor, *srcs, *total;
    float *dinv, *hid;
    __half *h1, *h2;
    cudaGetSymbolAddress((void**)&cnt, g_cnt);
    cudaGetSymbolAddress((void**)&off, g_off);
    cudaGetSymbolAddress((void**)&cursor, g_cursor);
    cudaGetSymbolAddress((void**)&srcs, g_srcs);
    cudaGetSymbolAddress((void**)&total, g_total);
    cudaGetSymbolAddress((void**)&dinv, g_dinv);
    cudaGetSymbolAddress((void**)&h1, g_h1);
    cudaGetSymbolAddress((void**)&hid, g_hid);
    cudaGetSymbolAddress((void**)&h2, g_h2);

    const int T = 256;
    int nBlkN = (N + T - 1) / T;
    int nBlkE = (E + T - 1) / T;
    int nBlkG = (N + 127) / 128;
    int nBlkGa = (N * 16 + T - 1) / T;

    // CSR build
    zero_cnt_kernel<<<nBlkN, T>>>(cnt, total, N);
    hist_kernel<<<nBlkE, T>>>(dst, cnt, E);
    dinv_kernel<<<nBlkN, T>>>(cnt, dinv, N);
    offsets_kernel<<<nBlkN, T>>>(cnt, off, cursor, total, N);
    reorder_kernel<<<nBlkE, T>>>(src, dst, cursor, srcs, E);

    // layer 1
    gemm_scaled_h_kernel<256><<<nBlkG, T>>>(x, W1, dinv, h1, N);
    gather_kernel<true><<<nBlkGa, T>>>((const uint2*)h1, off, cnt, srcs, dinv, b1,
                                       (float4*)hid, N);

    // layer 2
    gemm_scaled_h_kernel<64><<<nBlkG, T>>>(hid, W2, dinv, h2, N);
    gather_kernel<false><<<nBlkGa, T>>>((const uint2*)h2, off, cnt, srcs, dinv, b2,
                                        (float4*)out, N);
}

// round 7
// speedup vs baseline: 2.6418x; 1.2254x over previous
#include <cuda_runtime.h>
#include <cuda_fp16.h>
#include <cstdint>

#define MAX_NODES 100000
#define MAX_EDGES 3200000
#define HID 64

// Scratch (__device__ globals; 16B aligned)
__device__ __align__(16) int    g_cnt[MAX_NODES];
__device__ __align__(16) int    g_off[MAX_NODES];
__device__ __align__(16) int    g_cursor[MAX_NODES];
__device__ __align__(16) int    g_srcs[MAX_EDGES];
__device__                int   g_total;
__device__ __align__(16) float  g_dinv[MAX_NODES];
__device__ __align__(16) __half g_h1[MAX_NODES * HID];   // h1' = (x@W1)*dinv, fp16
__device__ __align__(16) float  g_hid[MAX_NODES * HID];  // relu'd hidden (fp32, GEMM2 A)
__device__ __align__(16) __half g_h2[MAX_NODES * HID];   // h2' = (hid@W2)*dinv, fp16

// ---------------------------------------------------------------------------
// CSR construction: histogram -> decoupled offsets -> reorder
// ---------------------------------------------------------------------------
__global__ void zero_cnt_kernel(int* cnt, int* total, int N) {
    int i = blockIdx.x * blockDim.x + threadIdx.x;
    if (i < N) cnt[i] = 0;
    if (i == 0) *total = 0;
}

__global__ void hist_kernel(const int* __restrict__ dst, int* cnt, int E) {
    int i = blockIdx.x * blockDim.x + threadIdx.x;
    if (i < E) atomicAdd(&cnt[dst[i]], 1);
}

__global__ void dinv_kernel(const int* __restrict__ cnt, float* dinv, int N) {
    int i = blockIdx.x * blockDim.x + threadIdx.x;
    if (i < N) dinv[i] = rsqrtf((float)cnt[i] + 1.0f);  // +1 self-loop
}

// Per-block scan + one atomicAdd per block for the base (segment order arbitrary).
__launch_bounds__(256)
__global__ void offsets_kernel(const int* __restrict__ cnt, int* off, int* cursor,
                               int* total, int N) {
    const int tid = threadIdx.x;
    const int i = blockIdx.x * 256 + tid;
    const int lane = tid & 31;
    const int warp = tid >> 5;

    int c = (i < N) ? cnt[i] : 0;

    int incl = c;
#pragma unroll
    for (int d = 1; d < 32; d <<= 1) {
        int v = __shfl_up_sync(0xFFFFFFFFu, incl, d);
        if (lane >= d) incl += v;
    }

    __shared__ int wsum[8];
    __shared__ int base;
    if (lane == 31) wsum[warp] = incl;
    __syncthreads();
    if (warp == 0) {
        int w = (lane < 8) ? wsum[lane] : 0;
#pragma unroll
        for (int d = 1; d < 8; d <<= 1) {
            int v = __shfl_up_sync(0xFFFFFFFFu, w, d);
            if (lane >= d) w += v;
        }
        if (lane < 8) wsum[lane] = w;
    }
    __syncthreads();
    int inclTotal = incl + ((warp > 0) ? wsum[warp - 1] : 0);
    if (tid == 255) base = atomicAdd(total, inclTotal);
    __syncthreads();
    if (i < N) {
        int o = base + inclTotal - c;
        off[i] = o;
        cursor[i] = o;
    }
}

__global__ void reorder_kernel(const int* __restrict__ src, const int* __restrict__ dst,
                               int* cursor, int* srcs, int E) {
    int i = blockIdx.x * blockDim.x + threadIdx.x;
    if (i < E) {
        int d = dst[i];
        int p = atomicAdd(&cursor[d], 1);
        srcs[p] = src[i];
    }
}

// ---------------------------------------------------------------------------
// tf32 tensor-core GEMM: C[r,:] = half( (A[r,:] @ B) * dinv[r] )
// BM=128, BN=64, BK=32; 256 threads = 8 warps (4 in m, 2 in n), warp tile 32x32.
// mma.sync.m16n8k8.tf32; A smem [m][k] stride 36, B smem [k][n] stride 72
// (both conflict-free for fragment LDS and STS.128 phases).
// ---------------------------------------------------------------------------
__device__ __forceinline__ unsigned f2tf32(float f) {
    unsigned u;
    asm("cvt.rna.tf32.f32 %0, %1;" : "=r"(u) : "f"(f));
    return u;
}

__device__ __forceinline__ void mma_tf32(float* c, const unsigned* a, const unsigned* b) {
    asm volatile(
        "mma.sync.aligned.m16n8k8.row.col.f32.tf32.tf32.f32 "
        "{%0,%1,%2,%3}, {%4,%5,%6,%7}, {%8,%9}, {%0,%1,%2,%3};"
        : "+f"(c[0]), "+f"(c[1]), "+f"(c[2]), "+f"(c[3])
        : "r"(a[0]), "r"(a[1]), "r"(a[2]), "r"(a[3]), "r"(b[0]), "r"(b[1]));
}

template <int K>
__launch_bounds__(256)
__global__ void gemm_tf32_kernel(const float* __restrict__ A, const float* __restrict__ Bm,
                                 const float* __restrict__ dinv, __half* __restrict__ C,
                                 int M) {
    constexpr int BM = 128, BK = 32;
    constexpr int ASTR = 36;  // 36 % 32 == 4 -> frag bank = 4*k + m-in-quad pattern
    constexpr int BSTR = 72;  // 72 % 32 == 8 -> frag bank = 8*k + n pattern
    __shared__ unsigned As[BM][ASTR];
    __shared__ unsigned Bs[BK][BSTR];

    const int tid = threadIdx.x;
    const int lane = tid & 31;
    const int warp = tid >> 5;
    const int wm = (warp & 3) * 32;   // warp row offset
    const int wn = (warp >> 2) * 32;  // warp col offset
    const int block_row = blockIdx.x * BM;
    const int g = lane >> 2;   // group id (0..7)
    const int tg = lane & 3;   // thread-in-group (0..3)

    float acc[2][4][4];
#pragma unroll
    for (int mi = 0; mi < 2; mi++)
#pragma unroll
        for (int na = 0; na < 4; na++)
#pragma unroll
            for (int r = 0; r < 4; r++) acc[mi][na][r] = 0.f;

    for (int k0 = 0; k0 < K; k0 += BK) {
        // A tile: 128x32 fp32 = 1024 float4; 4 per thread; cvt to tf32 on store
#pragma unroll
        for (int i = 0; i < 4; i++) {
            int idx = tid + i * 256;
            int r = idx >> 3;
            int c4 = (idx & 7) * 4;
            int grow = block_row + r;
            float4 v = make_float4(0.f, 0.f, 0.f, 0.f);
            if (grow < M)
                v = *reinterpret_cast<const float4*>(&A[(size_t)grow * K + k0 + c4]);
            uint4 u = make_uint4(f2tf32(v.x), f2tf32(v.y), f2tf32(v.z), f2tf32(v.w));
            *reinterpret_cast<uint4*>(&As[r][c4]) = u;
        }
        // B tile: 32x64 fp32 = 512 float4; 2 per thread
#pragma unroll
        for (int i = 0; i < 2; i++) {
            int idx = tid + i * 256;
            int r = idx >> 4;
            int c4 = (idx & 15) * 4;
            float4 v = *reinterpret_cast<const float4*>(&Bm[(size_t)(k0 + r) * 64 + c4]);
            uint4 u = make_uint4(f2tf32(v.x), f2tf32(v.y), f2tf32(v.z), f2tf32(v.w));
            *reinterpret_cast<uint4*>(&Bs[r][c4]) = u;
        }
        __syncthreads();

#pragma unroll
        for (int ks = 0; ks < 4; ks++) {
            const int kb = ks * 8;
            unsigned a[2][4], b[4][2];
#pragma unroll
            for (int mi = 0; mi < 2; mi++) {
                int row = wm + mi * 16 + g;
                a[mi][0] = As[row][kb + tg];
                a[mi][1] = As[row + 8][kb + tg];
                a[mi][2] = As[row][kb + tg + 4];
                a[mi][3] = As[row + 8][kb + tg + 4];
            }
#pragma unroll
            for (int na = 0; na < 4; na++) {
                int col = wn + na * 8 + g;
                b[na][0] = Bs[kb + tg][col];
                b[na][1] = Bs[kb + tg + 4][col];
            }
#pragma unroll
            for (int mi = 0; mi < 2; mi++)
#pragma unroll
                for (int na = 0; na < 4; na++) mma_tf32(acc[mi][na], a[mi], b[na]);
        }
        __syncthreads();
    }

    // epilogue: scale by dinv[row], convert to fp16, store half2
#pragma unroll
    for (int mi = 0; mi < 2; mi++) {
        int row_lo = block_row + wm + mi * 16 + g;
        int row_hi = row_lo + 8;
        float s_lo = (row_lo < M) ? dinv[row_lo] : 0.f;
        float s_hi = (row_hi < M) ? dinv[row_hi] : 0.f;
#pragma unroll
        for (int na = 0; na < 4; na++) {
            int col = wn + na * 8 + 2 * tg;
            if (row_lo < M) {
                __half2 h = __floats2half2_rn(acc[mi][na][0] * s_lo, acc[mi][na][1] * s_lo);
                *reinterpret_cast<__half2*>(&C[(size_t)row_lo * 64 + col]) = h;
            }
            if (row_hi < M) {
                __half2 h = __floats2half2_rn(acc[mi][na][2] * s_hi, acc[mi][na][3] * s_hi);
                *reinterpret_cast<__half2*>(&C[(size_t)row_hi * 64 + col]) = h;
            }
        }
    }
}

// ---------------------------------------------------------------------------
// Gather-reduce (fp16 table): out[d] = dinv[d]*(h'[d] + sum h'[src]) + bias
// 16 threads/node; each lane owns 4 channels via one uint2 (4 halves) per row.
// ---------------------------------------------------------------------------
__device__ __forceinline__ void acc_half4(float4& acc, uint2 u) {
    __half2 h0 = *reinterpret_cast<const __half2*>(&u.x);
    __half2 h1 = *reinterpret_cast<const __half2*>(&u.y);
    float2 f0 = __half22float2(h0);
    float2 f1 = __half22float2(h1);
    acc.x += f0.x; acc.y += f0.y; acc.z += f1.x; acc.w += f1.y;
}

template <bool RELU>
__global__ void gather_kernel(const uint2* __restrict__ hs, const int* __restrict__ off,
                              const int* __restrict__ cnt, const int* __restrict__ srcs,
                              const float* __restrict__ dinv, const float* __restrict__ bias,
                              float4* __restrict__ out, int N) {
    int i = blockIdx.x * blockDim.x + threadIdx.x;
    if (i >= N * 16) return;
    int node = i >> 4;
    int lane = i & 15;

    float4 acc = make_float4(0.f, 0.f, 0.f, 0.f);
    acc_half4(acc, hs[(size_t)node * 16 + lane]);  // self-loop term
    int e = off[node];
    const int end = e + cnt[node];

    for (; e + 4 <= end; e += 4) {
        int s0 = srcs[e], s1 = srcs[e + 1], s2 = srcs[e + 2], s3 = srcs[e + 3];
        uint2 v0 = hs[(size_t)s0 * 16 + lane];
        uint2 v1 = hs[(size_t)s1 * 16 + lane];
        uint2 v2 = hs[(size_t)s2 * 16 + lane];
        uint2 v3 = hs[(size_t)s3 * 16 + lane];
        acc_half4(acc, v0); acc_half4(acc, v1);
        acc_half4(acc, v2); acc_half4(acc, v3);
    }
    for (; e < end; e++) {
        acc_half4(acc, hs[(size_t)srcs[e] * 16 + lane]);
    }

    float dd = dinv[node];
    float4 bv = reinterpret_cast<const float4*>(bias)[lane];
    float r0 = fmaf(acc.x, dd, bv.x);
    float r1 = fmaf(acc.y, dd, bv.y);
    float r2 = fmaf(acc.z, dd, bv.z);
    float r3 = fmaf(acc.w, dd, bv.w);
    if (RELU) {
        r0 = fmaxf(r0, 0.f); r1 = fmaxf(r1, 0.f);
        r2 = fmaxf(r2, 0.f); r3 = fmaxf(r3, 0.f);
    }
    out[(size_t)node * 16 + lane] = make_float4(r0, r1, r2, r3);
}

// ---------------------------------------------------------------------------
// launch
// ---------------------------------------------------------------------------
extern "C" void kernel_launch(void* const* d_in, const int* in_sizes, int n_in,
                              void* d_out, int out_size) {
    const float* x = (const float*)d_in[0];
    const int* edge_index = (const int*)d_in[1];
    const float* W1 = (const float*)d_in[2];
    const float* b1 = (const float*)d_in[3];
    const float* W2 = (const float*)d_in[4];
    const float* b2 = (const float*)d_in[5];
    float* out = (float*)d_out;

    const int IN_CH = 256;
    const int N = in_sizes[0] / IN_CH;  // 100000
    const int E = in_sizes[1] / 2;      // 3200000
    const int* src = edge_index;
    const int* dst = edge_index + E;

    int *cnt, *off, *cursor, *srcs, *total;
    float *dinv, *hid;
    __half *h1, *h2;
    cudaGetSymbolAddress((void**)&cnt, g_cnt);
    cudaGetSymbolAddress((void**)&off, g_off);
    cudaGetSymbolAddress((void**)&cursor, g_cursor);
    cudaGetSymbolAddress((void**)&srcs, g_srcs);
    cudaGetSymbolAddress((void**)&total, g_total);
    cudaGetSymbolAddress((void**)&dinv, g_dinv);
    cudaGetSymbolAddress((void**)&h1, g_h1);
    cudaGetSymbolAddress((void**)&hid, g_hid);
    cudaGetSymbolAddress((void**)&h2, g_h2);

    const int T = 256;
    int nBlkN = (N + T - 1) / T;
    int nBlkE = (E + T - 1) / T;
    int nBlkG = (N + 127) / 128;
    int nBlkGa = (N * 16 + T - 1) / T;

    // CSR build
    zero_cnt_kernel<<<nBlkN, T>>>(cnt, total, N);
    hist_kernel<<<nBlkE, T>>>(dst, cnt, E);
    dinv_kernel<<<nBlkN, T>>>(cnt, dinv, N);
    offsets_kernel<<<nBlkN, T>>>(cnt, off, cursor, total, N);
    reorder_kernel<<<nBlkE, T>>>(src, dst, cursor, srcs, E);

    // layer 1
    gemm_tf32_kernel<256><<<nBlkG, T>>>(x, W1, dinv, h1, N);
    gather_kernel<true><<<nBlkGa, T>>>((const uint2*)h1, off, cnt, srcs, dinv, b1,
                                       (float4*)hid, N);

    // layer 2
    gemm_tf32_kernel<64><<<nBlkG, T>>>(hid, W2, dinv, h2, N);
    gather_kernel<false><<<nBlkGa, T>>>((const uint2*)h2, off, cnt, srcs, dinv, b2,
                                        (float4*)out, N);
}

// round 9
// speedup vs baseline: 2.6987x; 1.0215x over previous
#include <cuda_runtime.h>
#include <cuda_fp16.h>
#include <cstdint>

#define MAX_NODES 100000
#define MAX_EDGES 3200000
#define HID 64

// Scratch (__device__ globals; 16B aligned)
__device__ __align__(16) int    g_cnt[MAX_NODES];
__device__ __align__(16) int    g_off[MAX_NODES];
__device__ __align__(16) int    g_rank[MAX_EDGES];
__device__ __align__(16) int    g_srcs[MAX_EDGES];
__device__                int   g_total;
__device__ __align__(16) float  g_dinv[MAX_NODES];
__device__ __align__(16) __half g_h1[MAX_NODES * HID];   // h1' = (x@W1)*dinv, fp16
__device__ __align__(16) float  g_hid[MAX_NODES * HID];  // relu'd hidden (fp32)
__device__ __align__(16) __half g_h2[MAX_NODES * HID];   // h2' = (hid@W2)*dinv, fp16

// ---------------------------------------------------------------------------
// CSR construction
// ---------------------------------------------------------------------------
__global__ void zero_cnt_kernel(int* cnt, int* total, int N) {
    int i = blockIdx.x * blockDim.x + threadIdx.x;
    if (i < N) cnt[i] = 0;
    if (i == 0) *total = 0;
}

// histogram + per-edge rank within its dst bucket (from the atomic's return)
__global__ void hist_rank_kernel(const int* __restrict__ dst, int* cnt,
                                 int* __restrict__ rank, int E) {
    int i = blockIdx.x * blockDim.x + threadIdx.x;
    if (i < E) rank[i] = atomicAdd(&cnt[dst[i]], 1);
}

// Per-block scan + one atomicAdd per block for base (segment order arbitrary).
// Also computes dinv here (fused).
__launch_bounds__(256)
__global__ void offsets_dinv_kernel(const int* __restrict__ cnt, int* off,
                                    float* __restrict__ dinv, int* total, int N) {
    const int tid = threadIdx.x;
    const int i = blockIdx.x * 256 + tid;
    const int lane = tid & 31;
    const int warp = tid >> 5;

    int c = (i < N) ? cnt[i] : 0;

    int incl = c;
#pragma unroll
    for (int d = 1; d < 32; d <<= 1) {
        int v = __shfl_up_sync(0xFFFFFFFFu, incl, d);
        if (lane >= d) incl += v;
    }

    __shared__ int wsum[8];
    __shared__ int base;
    if (lane == 31) wsum[warp] = incl;
    __syncthreads();
    if (warp == 0) {
        int w = (lane < 8) ? wsum[lane] : 0;
#pragma unroll
        for (int d = 1; d < 8; d <<= 1) {
            int v = __shfl_up_sync(0xFFFFFFFFu, w, d);
            if (lane >= d) w += v;
        }
        if (lane < 8) wsum[lane] = w;
    }
    __syncthreads();
    int inclTotal = incl + ((warp > 0) ? wsum[warp - 1] : 0);
    if (tid == 255) base = atomicAdd(total, inclTotal);
    __syncthreads();
    if (i < N) {
        off[i] = base + inclTotal - c;
        dinv[i] = rsqrtf((float)c + 1.0f);  // +1 self-loop
    }
}

// ---------------------------------------------------------------------------
// tf32 tensor-core GEMM body (device function so it can be fused)
// C[r,:] = half( (A[r,:] @ B) * dinv[r] );  BM=128, BN=64, BK=32, 8 warps.
// ---------------------------------------------------------------------------
__device__ __forceinline__ unsigned f2tf32(float f) {
    unsigned u;
    asm("cvt.rna.tf32.f32 %0, %1;" : "=r"(u) : "f"(f));
    return u;
}

__device__ __forceinline__ void mma_tf32(float* c, const unsigned* a, const unsigned* b) {
    asm volatile(
        "mma.sync.aligned.m16n8k8.row.col.f32.tf32.tf32.f32 "
        "{%0,%1,%2,%3}, {%4,%5,%6,%7}, {%8,%9}, {%0,%1,%2,%3};"
        : "+f"(c[0]), "+f"(c[1]), "+f"(c[2]), "+f"(c[3])
        : "r"(a[0]), "r"(a[1]), "r"(a[2]), "r"(a[3]), "r"(b[0]), "r"(b[1]));
}

template <int K>
__device__ __forceinline__ void gemm_tf32_body(
    const float* __restrict__ A, const float* __restrict__ Bm,
    const float* __restrict__ dinv, __half* __restrict__ C, int M, int bidx) {
    constexpr int BM = 128, BK = 32;
    constexpr int ASTR = 36;
    constexpr int BSTR = 72;
    __shared__ unsigned As[BM][ASTR];
    __shared__ unsigned Bs[BK][BSTR];

    const int tid = threadIdx.x;
    const int lane = tid & 31;
    const int warp = tid >> 5;
    const int wm = (warp & 3) * 32;
    const int wn = (warp >> 2) * 32;
    const int block_row = bidx * BM;
    const int g = lane >> 2;
    const int tg = lane & 3;

    float acc[2][4][4];
#pragma unroll
    for (int mi = 0; mi < 2; mi++)
#pragma unroll
        for (int na = 0; na < 4; na++)
#pragma unroll
            for (int r = 0; r < 4; r++) acc[mi][na][r] = 0.f;

    for (int k0 = 0; k0 < K; k0 += BK) {
#pragma unroll
        for (int i = 0; i < 4; i++) {
            int idx = tid + i * 256;
            int r = idx >> 3;
            int c4 = (idx & 7) * 4;
            int grow = block_row + r;
            float4 v = make_float4(0.f, 0.f, 0.f, 0.f);
            if (grow < M)
                v = *reinterpret_cast<const float4*>(&A[(size_t)grow * K + k0 + c4]);
            uint4 u = make_uint4(f2tf32(v.x), f2tf32(v.y), f2tf32(v.z), f2tf32(v.w));
            *reinterpret_cast<uint4*>(&As[r][c4]) = u;
        }
#pragma unroll
        for (int i = 0; i < 2; i++) {
            int idx = tid + i * 256;
            int r = idx >> 4;
            int c4 = (idx & 15) * 4;
            float4 v = *reinterpret_cast<const float4*>(&Bm[(size_t)(k0 + r) * 64 + c4]);
            uint4 u = make_uint4(f2tf32(v.x), f2tf32(v.y), f2tf32(v.z), f2tf32(v.w));
            *reinterpret_cast<uint4*>(&Bs[r][c4]) = u;
        }
        __syncthreads();

#pragma unroll
        for (int ks = 0; ks < 4; ks++) {
            const int kb = ks * 8;
            unsigned a[2][4], b[4][2];
#pragma unroll
            for (int mi = 0; mi < 2; mi++) {
                int row = wm + mi * 16 + g;
                a[mi][0] = As[row][kb + tg];
                a[mi][1] = As[row + 8][kb + tg];
                a[mi][2] = As[row][kb + tg + 4];
                a[mi][3] = As[row + 8][kb + tg + 4];
            }
#pragma unroll
            for (int na = 0; na < 4; na++) {
                int col = wn + na * 8 + g;
                b[na][0] = Bs[kb + tg][col];
                b[na][1] = Bs[kb + tg + 4][col];
            }
#pragma unroll
            for (int mi = 0; mi < 2; mi++)
#pragma unroll
                for (int na = 0; na < 4; na++) mma_tf32(acc[mi][na], a[mi], b[na]);
        }
        __syncthreads();
    }

#pragma unroll
    for (int mi = 0; mi < 2; mi++) {
        int row_lo = block_row + wm + mi * 16 + g;
        int row_hi = row_lo + 8;
        float s_lo = (row_lo < M) ? dinv[row_lo] : 0.f;
        float s_hi = (row_hi < M) ? dinv[row_hi] : 0.f;
#pragma unroll
        for (int na = 0; na < 4; na++) {
            int col = wn + na * 8 + 2 * tg;
            if (row_lo < M) {
                __half2 h = __floats2half2_rn(acc[mi][na][0] * s_lo, acc[mi][na][1] * s_lo);
                *reinterpret_cast<__half2*>(&C[(size_t)row_lo * 64 + col]) = h;
            }
            if (row_hi < M) {
                __half2 h = __floats2half2_rn(acc[mi][na][2] * s_hi, acc[mi][na][3] * s_hi);
                *reinterpret_cast<__half2*>(&C[(size_t)row_hi * 64 + col]) = h;
            }
        }
    }
}

// standalone GEMM (layer 2)
template <int K>
__launch_bounds__(256)
__global__ void gemm_tf32_kernel(const float* __restrict__ A, const float* __restrict__ Bm,
                                 const float* __restrict__ dinv, __half* __restrict__ C,
                                 int M) {
    gemm_tf32_body<K>(A, Bm, dinv, C, M, blockIdx.x);
}

// Fused: blocks [0,nG) do GEMM1; blocks [nG, nG+nR) do atomic-free reorder.
// The two are independent (both depend only on offsets_dinv + hist).
__launch_bounds__(256)
__global__ void fused_gemm1_reorder_kernel(
    const float* __restrict__ A, const float* __restrict__ Bm,
    const float* __restrict__ dinv, __half* __restrict__ C, int M, int nG,
    const int* __restrict__ src, const int* __restrict__ dst,
    const int* __restrict__ rank, const int* __restrict__ off,
    int* __restrict__ srcs, int E) {
    if (blockIdx.x < nG) {
        gemm_tf32_body<256>(A, Bm, dinv, C, M, blockIdx.x);
    } else {
        int i = (blockIdx.x - nG) * 256 + threadIdx.x;
        if (i < E) {
            int d = dst[i];
            srcs[off[d] + rank[i]] = src[i];
        }
    }
}

// ---------------------------------------------------------------------------
// Gather-reduce (fp16 table): out[d] = dinv[d]*(h'[d] + sum h'[src]) + bias
// ---------------------------------------------------------------------------
__device__ __forceinline__ void acc_half4(float4& acc, uint2 u) {
    __half2 h0 = *reinterpret_cast<const __half2*>(&u.x);
    __half2 h1 = *reinterpret_cast<const __half2*>(&u.y);
    float2 f0 = __half22float2(h0);
    float2 f1 = __half22float2(h1);
    acc.x += f0.x; acc.y += f0.y; acc.z += f1.x; acc.w += f1.y;
}

template <bool RELU>
__global__ void gather_kernel(const uint2* __restrict__ hs, const int* __restrict__ off,
                              const int* __restrict__ cnt, const int* __restrict__ srcs,
                              const float* __restrict__ dinv, const float* __restrict__ bias,
                              float4* __restrict__ out, int N) {
    int i = blockIdx.x * blockDim.x + threadIdx.x;
    if (i >= N * 16) return;
    int node = i >> 4;
    int lane = i & 15;

    float4 acc = make_float4(0.f, 0.f, 0.f, 0.f);
    acc_half4(acc, hs[(size_t)node * 16 + lane]);  // self-loop term
    int e = off[node];
    const int end = e + cnt[node];

    for (; e + 4 <= end; e += 4) {
        int s0 = srcs[e], s1 = srcs[e + 1], s2 = srcs[e + 2], s3 = srcs[e + 3];
        uint2 v0 = hs[(size_t)s0 * 16 + lane];
        uint2 v1 = hs[(size_t)s1 * 16 + lane];
        uint2 v2 = hs[(size_t)s2 * 16 + lane];
        uint2 v3 = hs[(size_t)s3 * 16 + lane];
        acc_half4(acc, v0); acc_half4(acc, v1);
        acc_half4(acc, v2); acc_half4(acc, v3);
    }
    for (; e < end; e++) {
        acc_half4(acc, hs[(size_t)srcs[e] * 16 + lane]);
    }

    float dd = dinv[node];
    float4 bv = reinterpret_cast<const float4*>(bias)[lane];
    float r0 = fmaf(acc.x, dd, bv.x);
    float r1 = fmaf(acc.y, dd, bv.y);
    float r2 = fmaf(acc.z, dd, bv.z);
    float r3 = fmaf(acc.w, dd, bv.w);
    if (RELU) {
        r0 = fmaxf(r0, 0.f); r1 = fmaxf(r1, 0.f);
        r2 = fmaxf(r2, 0.f); r3 = fmaxf(r3, 0.f);
    }
    out[(size_t)node * 16 + lane] = make_float4(r0, r1, r2, r3);
}

// ---------------------------------------------------------------------------
// launch
// ---------------------------------------------------------------------------
extern "C" void kernel_launch(void* const* d_in, const int* in_sizes, int n_in,
                              void* d_out, int out_size) {
    const float* x = (const float*)d_in[0];
    const int* edge_index = (const int*)d_in[1];
    const float* W1 = (const float*)d_in[2];
    const float* b1 = (const float*)d_in[3];
    const float* W2 = (const float*)d_in[4];
    const float* b2 = (const float*)d_in[5];
    float* out = (float*)d_out;

    const int IN_CH = 256;
    const int N = in_sizes[0] / IN_CH;  // 100000
    const int E = in_sizes[1] / 2;      // 3200000
    const int* src = edge_index;
    const int* dst = edge_index + E;

    int *cnt, *off, *rank, *srcs, *total;
    float *dinv, *hid;
    __half *h1, *h2;
    cudaGetSymbolAddress((void**)&cnt, g_cnt);
    cudaGetSymbolAddress((void**)&off, g_off);
    cudaGetSymbolAddress((void**)&rank, g_rank);
    cudaGetSymbolAddress((void**)&srcs, g_srcs);
    cudaGetSymbolAddress((void**)&total, g_total);
    cudaGetSymbolAddress((void**)&dinv, g_dinv);
    cudaGetSymbolAddress((void**)&h1, g_h1);
    cudaGetSymbolAddress((void**)&hid, g_hid);
    cudaGetSymbolAddress((void**)&h2, g_h2);

    const int T = 256;
    int nBlkN = (N + T - 1) / T;
    int nBlkE = (E + T - 1) / T;
    int nBlkG = (N + 127) / 128;
    int nBlkGa = (N * 16 + T - 1) / T;

    // CSR build (phase 1)
    zero_cnt_kernel<<<nBlkN, T>>>(cnt, total, N);
    hist_rank_kernel<<<nBlkE, T>>>(dst, cnt, rank, E);
    offsets_dinv_kernel<<<nBlkN, T>>>(cnt, off, dinv, total, N);

    // phase 2: GEMM1 and reorder overlap in one launch (independent work)
    fused_gemm1_reorder_kernel<<<nBlkG + nBlkE, T>>>(
        x, W1, dinv, h1, N, nBlkG, src, dst, rank, off, srcs, E);

    // layer 1 aggregation
    gather_kernel<true><<<nBlkGa, T>>>((const uint2*)h1, off, cnt, srcs, dinv, b1,
                                       (float4*)hid, N);

    // layer 2
    gemm_tf32_kernel<64><<<nBlkG, T>>>(hid, W2, dinv, h2, N);
    gather_kernel<false><<<nBlkGa, T>>>((const uint2*)h2, off, cnt, srcs, dinv, b2,
                                        (float4*)out, N);
}

// round 10
// speedup vs baseline: 2.8963x; 1.0732x over previous
#include <cuda_runtime.h>
#include <cuda_fp16.h>
#include <cstdint>

#define MAX_NODES 100000
#define MAX_EDGES 3200000
#define HID 64
#define CAP 128          // padded-CSR capacity per node (Poisson(32); max deg ~60)
#define MAX_SPILL 4096   // overflow list (expected empty)

// Scratch (__device__ globals; 16B aligned)
__device__ __align__(16) int    g_cnt[MAX_NODES];
__device__ __align__(16) int    g_srcs[MAX_NODES * CAP];  // padded CSR
__device__                int   g_nspill;
__device__ __align__(16) int    g_spill_d[MAX_SPILL];
__device__ __align__(16) int    g_spill_s[MAX_SPILL];
__device__ __align__(16) float  g_dinv[MAX_NODES];
__device__ __align__(16) __half g_h1[MAX_NODES * HID];   // h1' = (x@W1)*dinv, fp16
__device__ __align__(16) float  g_hid[MAX_NODES * HID];  // relu'd hidden (fp32)
__device__ __align__(16) __half g_h2[MAX_NODES * HID];   // h2' = (hid@W2)*dinv, fp16

// ---------------------------------------------------------------------------
// CSR construction (single pass, padded)
// ---------------------------------------------------------------------------
__global__ void zero_cnt_kernel(int* cnt, int* nspill, int N) {
    int i = blockIdx.x * blockDim.x + threadIdx.x;
    if (i < N) cnt[i] = 0;
    if (i == 0) *nspill = 0;
}

// histogram + direct scatter into padded CSR (rank = atomic return value)
__global__ void hist_scatter_kernel(const int* __restrict__ src, const int* __restrict__ dst,
                                    int* cnt, int* __restrict__ srcs,
                                    int* nspill, int* spill_d, int* spill_s, int E) {
    int i = blockIdx.x * blockDim.x + threadIdx.x;
    if (i >= E) return;
    int s = src[i];
    int d = dst[i];
    int r = atomicAdd(&cnt[d], 1);
    if (r < CAP) {
        srcs[d * CAP + r] = s;
    } else {  // effectively never taken (Poisson(32) vs CAP=128)
        int k = atomicAdd(nspill, 1);
        if (k < MAX_SPILL) { spill_d[k] = d; spill_s[k] = s; }
    }
}

__global__ void dinv_kernel(const int* __restrict__ cnt, float* dinv, int N) {
    int i = blockIdx.x * blockDim.x + threadIdx.x;
    if (i < N) dinv[i] = rsqrtf((float)cnt[i] + 1.0f);  // +1 self-loop
}

// ---------------------------------------------------------------------------
// tf32 tensor-core GEMM: C[r,:] = half( (A[r,:] @ B) * dinv[r] )
// BM=128, BN=64, BK=32; 256 threads = 8 warps (4 m × 2 n), warp tile 32x32.
// ---------------------------------------------------------------------------
__device__ __forceinline__ unsigned f2tf32(float f) {
    unsigned u;
    asm("cvt.rna.tf32.f32 %0, %1;" : "=r"(u) : "f"(f));
    return u;
}

__device__ __forceinline__ void mma_tf32(float* c, const unsigned* a, const unsigned* b) {
    asm volatile(
        "mma.sync.aligned.m16n8k8.row.col.f32.tf32.tf32.f32 "
        "{%0,%1,%2,%3}, {%4,%5,%6,%7}, {%8,%9}, {%0,%1,%2,%3};"
        : "+f"(c[0]), "+f"(c[1]), "+f"(c[2]), "+f"(c[3])
        : "r"(a[0]), "r"(a[1]), "r"(a[2]), "r"(a[3]), "r"(b[0]), "r"(b[1]));
}

template <int K>
__launch_bounds__(256)
__global__ void gemm_tf32_kernel(const float* __restrict__ A, const float* __restrict__ Bm,
                                 const float* __restrict__ dinv, __half* __restrict__ C,
                                 int M) {
    constexpr int BM = 128, BK = 32;
    constexpr int ASTR = 36;  // conflict-free for frag LDS + STS.128
    constexpr int BSTR = 72;
    __shared__ unsigned As[BM][ASTR];
    __shared__ unsigned Bs[BK][BSTR];

    const int tid = threadIdx.x;
    const int lane = tid & 31;
    const int warp = tid >> 5;
    const int wm = (warp & 3) * 32;
    const int wn = (warp >> 2) * 32;
    const int block_row = blockIdx.x * BM;
    const int g = lane >> 2;
    const int tg = lane & 3;

    float acc[2][4][4];
#pragma unroll
    for (int mi = 0; mi < 2; mi++)
#pragma unroll
        for (int na = 0; na < 4; na++)
#pragma unroll
            for (int r = 0; r < 4; r++) acc[mi][na][r] = 0.f;

    for (int k0 = 0; k0 < K; k0 += BK) {
#pragma unroll
        for (int i = 0; i < 4; i++) {
            int idx = tid + i * 256;
            int r = idx >> 3;
            int c4 = (idx & 7) * 4;
            int grow = block_row + r;
            float4 v = make_float4(0.f, 0.f, 0.f, 0.f);
            if (grow < M)
                v = *reinterpret_cast<const float4*>(&A[(size_t)grow * K + k0 + c4]);
            uint4 u = make_uint4(f2tf32(v.x), f2tf32(v.y), f2tf32(v.z), f2tf32(v.w));
            *reinterpret_cast<uint4*>(&As[r][c4]) = u;
        }
#pragma unroll
        for (int i = 0; i < 2; i++) {
            int idx = tid + i * 256;
            int r = idx >> 4;
            int c4 = (idx & 15) * 4;
            float4 v = *reinterpret_cast<const float4*>(&Bm[(size_t)(k0 + r) * 64 + c4]);
            uint4 u = make_uint4(f2tf32(v.x), f2tf32(v.y), f2tf32(v.z), f2tf32(v.w));
            *reinterpret_cast<uint4*>(&Bs[r][c4]) = u;
        }
        __syncthreads();

#pragma unroll
        for (int ks = 0; ks < 4; ks++) {
            const int kb = ks * 8;
            unsigned a[2][4], b[4][2];
#pragma unroll
            for (int mi = 0; mi < 2; mi++) {
                int row = wm + mi * 16 + g;
                a[mi][0] = As[row][kb + tg];
                a[mi][1] = As[row + 8][kb + tg];
                a[mi][2] = As[row][kb + tg + 4];
                a[mi][3] = As[row + 8][kb + tg + 4];
            }
#pragma unroll
            for (int na = 0; na < 4; na++) {
                int col = wn + na * 8 + g;
                b[na][0] = Bs[kb + tg][col];
                b[na][1] = Bs[kb + tg + 4][col];
            }
#pragma unroll
            for (int mi = 0; mi < 2; mi++)
#pragma unroll
                for (int na = 0; na < 4; na++) mma_tf32(acc[mi][na], a[mi], b[na]);
        }
        __syncthreads();
    }

#pragma unroll
    for (int mi = 0; mi < 2; mi++) {
        int row_lo = block_row + wm + mi * 16 + g;
        int row_hi = row_lo + 8;
        float s_lo = (row_lo < M) ? dinv[row_lo] : 0.f;
        float s_hi = (row_hi < M) ? dinv[row_hi] : 0.f;
#pragma unroll
        for (int na = 0; na < 4; na++) {
            int col = wn + na * 8 + 2 * tg;
            if (row_lo < M) {
                __half2 h = __floats2half2_rn(acc[mi][na][0] * s_lo, acc[mi][na][1] * s_lo);
                *reinterpret_cast<__half2*>(&C[(size_t)row_lo * 64 + col]) = h;
            }
            if (row_hi < M) {
                __half2 h = __floats2half2_rn(acc[mi][na][2] * s_hi, acc[mi][na][3] * s_hi);
                *reinterpret_cast<__half2*>(&C[(size_t)row_hi * 64 + col]) = h;
            }
        }
    }
}

// ---------------------------------------------------------------------------
// Gather-reduce (fp16 table, padded CSR):
// out[d] = dinv[d]*(h'[d] + sum h'[src]) + bias
// ---------------------------------------------------------------------------
__device__ __forceinline__ void acc_half4(float4& acc, uint2 u) {
    __half2 h0 = *reinterpret_cast<const __half2*>(&u.x);
    __half2 h1 = *reinterpret_cast<const __half2*>(&u.y);
    float2 f0 = __half22float2(h0);
    float2 f1 = __half22float2(h1);
    acc.x += f0.x; acc.y += f0.y; acc.z += f1.x; acc.w += f1.y;
}

template <bool RELU>
__global__ void gather_kernel(const uint2* __restrict__ hs, const int* __restrict__ cnt,
                              const int* __restrict__ srcs, const float* __restrict__ dinv,
                              const float* __restrict__ bias,
                              const int* __restrict__ nspill, const int* __restrict__ spill_d,
                              const int* __restrict__ spill_s,
                              float4* __restrict__ out, int N) {
    int i = blockIdx.x * blockDim.x + threadIdx.x;
    if (i >= N * 16) return;
    int node = i >> 4;
    int lane = i & 15;

    float4 acc = make_float4(0.f, 0.f, 0.f, 0.f);
    acc_half4(acc, hs[(size_t)node * 16 + lane]);  // self-loop term
    const int c = cnt[node];
    int e = node * CAP;
    const int end = e + min(c, CAP);

    for (; e + 4 <= end; e += 4) {
        int s0 = srcs[e], s1 = srcs[e + 1], s2 = srcs[e + 2], s3 = srcs[e + 3];
        uint2 v0 = hs[(size_t)s0 * 16 + lane];
        uint2 v1 = hs[(size_t)s1 * 16 + lane];
        uint2 v2 = hs[(size_t)s2 * 16 + lane];
        uint2 v3 = hs[(size_t)s3 * 16 + lane];
        acc_half4(acc, v0); acc_half4(acc, v1);
        acc_half4(acc, v2); acc_half4(acc, v3);
    }
    for (; e < end; e++) {
        acc_half4(acc, hs[(size_t)srcs[e] * 16 + lane]);
    }

    if (c > CAP) {  // overflow fixup (empty in practice)
        int ns = min(*nspill, MAX_SPILL);
        for (int j = 0; j < ns; j++) {
            if (spill_d[j] == node) acc_half4(acc, hs[(size_t)spill_s[j] * 16 + lane]);
        }
    }

    float dd = dinv[node];
    float4 bv = reinterpret_cast<const float4*>(bias)[lane];
    float r0 = fmaf(acc.x, dd, bv.x);
    float r1 = fmaf(acc.y, dd, bv.y);
    float r2 = fmaf(acc.z, dd, bv.z);
    float r3 = fmaf(acc.w, dd, bv.w);
    if (RELU) {
        r0 = fmaxf(r0, 0.f); r1 = fmaxf(r1, 0.f);
        r2 = fmaxf(r2, 0.f); r3 = fmaxf(r3, 0.f);
    }
    out[(size_t)node * 16 + lane] = make_float4(r0, r1, r2, r3);
}

// ---------------------------------------------------------------------------
// launch
// ---------------------------------------------------------------------------
extern "C" void kernel_launch(void* const* d_in, const int* in_sizes, int n_in,
                              void* d_out, int out_size) {
    const float* x = (const float*)d_in[0];
    const int* edge_index = (const int*)d_in[1];
    const float* W1 = (const float*)d_in[2];
    const float* b1 = (const float*)d_in[3];
    const float* W2 = (const float*)d_in[4];
    const float* b2 = (const float*)d_in[5];
    float* out = (float*)d_out;

    const int IN_CH = 256;
    const int N = in_sizes[0] / IN_CH;  // 100000
    const int E = in_sizes[1] / 2;      // 3200000
    const int* src = edge_index;
    const int* dst = edge_index + E;

    int *cnt, *srcs, *nspill, *spill_d, *spill_s;
    float *dinv, *hid;
    __half *h1, *h2;
    cudaGetSymbolAddress((void**)&cnt, g_cnt);
    cudaGetSymbolAddress((void**)&srcs, g_srcs);
    cudaGetSymbolAddress((void**)&nspill, g_nspill);
    cudaGetSymbolAddress((void**)&spill_d, g_spill_d);
    cudaGetSymbolAddress((void**)&spill_s, g_spill_s);
    cudaGetSymbolAddress((void**)&dinv, g_dinv);
    cudaGetSymbolAddress((void**)&h1, g_h1);
    cudaGetSymbolAddress((void**)&hid, g_hid);
    cudaGetSymbolAddress((void**)&h2, g_h2);

    const int T = 256;
    int nBlkN = (N + T - 1) / T;
    int nBlkE = (E + T - 1) / T;
    int nBlkG = (N + 127) / 128;
    int nBlkGa = (N * 16 + T - 1) / T;

    // padded CSR build (single pass)
    zero_cnt_kernel<<<nBlkN, T>>>(cnt, nspill, N);
    hist_scatter_kernel<<<nBlkE, T>>>(src, dst, cnt, srcs, nspill, spill_d, spill_s, E);
    dinv_kernel<<<nBlkN, T>>>(cnt, dinv, N);

    // layer 1
    gemm_tf32_kernel<256><<<nBlkG, T>>>(x, W1, dinv, h1, N);
    gather_kernel<true><<<nBlkGa, T>>>((const uint2*)h1, cnt, srcs, dinv, b1,
                                       nspill, spill_d, spill_s, (float4*)hid, N);

    // layer 2
    gemm_tf32_kernel<64><<<nBlkG, T>>>(hid, W2, dinv, h2, N);
    gather_kernel<false><<<nBlkGa, T>>>((const uint2*)h2, cnt, srcs, dinv, b2,
                                        nspill, spill_d, spill_s, (float4*)out, N);
}

// round 11
// speedup vs baseline: 3.1274x; 1.0798x over previous
#include <cuda_runtime.h>
#include <cuda_fp16.h>
#include <cstdint>

#define MAX_NODES 100000
#define MAX_EDGES 3200000
#define HID 64
#define CAP 128          // padded-CSR capacity per node (Poisson(32); max deg ~60)
#define MAX_SPILL 4096   // overflow list (expected empty)

// Scratch (__device__ globals; 16B aligned)
__device__ __align__(16) int    g_cnt[MAX_NODES];
__device__ __align__(16) int    g_srcs[MAX_NODES * CAP];  // padded CSR
__device__                int   g_nspill;
__device__ __align__(16) int    g_spill_d[MAX_SPILL];
__device__ __align__(16) int    g_spill_s[MAX_SPILL];
__device__ __align__(16) float  g_dinv[MAX_NODES];
__device__ __align__(16) __half g_h1[MAX_NODES * HID];   // h1' = (x@W1)*dinv, fp16
__device__ __align__(16) float  g_hid[MAX_NODES * HID];  // relu'd hidden (fp32)
__device__ __align__(16) __half g_h2[MAX_NODES * HID];   // h2' = (hid@W2)*dinv, fp16

// ---------------------------------------------------------------------------
// CSR construction (single pass, padded)
// ---------------------------------------------------------------------------
__global__ void zero_cnt_kernel(int* cnt, int* nspill, int N) {
    int i = blockIdx.x * blockDim.x + threadIdx.x;
    if (i < N) cnt[i] = 0;
    if (i == 0) *nspill = 0;
}

__global__ void hist_scatter_kernel(const int* __restrict__ src, const int* __restrict__ dst,
                                    int* cnt, int* __restrict__ srcs,
                                    int* nspill, int* spill_d, int* spill_s, int E) {
    int i = blockIdx.x * blockDim.x + threadIdx.x;
    if (i >= E) return;
    int s = src[i];
    int d = dst[i];
    int r = atomicAdd(&cnt[d], 1);
    if (r < CAP) {
        srcs[d * CAP + r] = s;
    } else {
        int k = atomicAdd(nspill, 1);
        if (k < MAX_SPILL) { spill_d[k] = d; spill_s[k] = s; }
    }
}

__global__ void dinv_kernel(const int* __restrict__ cnt, float* dinv, int N) {
    int i = blockIdx.x * blockDim.x + threadIdx.x;
    if (i < N) dinv[i] = rsqrtf((float)cnt[i] + 1.0f);  // +1 self-loop
}

// ---------------------------------------------------------------------------
// tf32 tensor-core GEMM, cp.async double-buffered.
// C[r,:] = half( (A[r,:] @ B) * dinv[r] );  BM=128, BN=64, BK=32; 8 warps.
// Tiles staged fp32 in smem (L1-bypass); tf32 cvt at fragment load.
// ---------------------------------------------------------------------------
__device__ __forceinline__ unsigned f2tf32(float f) {
    unsigned u;
    asm("cvt.rna.tf32.f32 %0, %1;" : "=r"(u) : "f"(f));
    return u;
}

__device__ __forceinline__ void mma_tf32(float* c, const unsigned* a, const unsigned* b) {
    asm volatile(
        "mma.sync.aligned.m16n8k8.row.col.f32.tf32.tf32.f32 "
        "{%0,%1,%2,%3}, {%4,%5,%6,%7}, {%8,%9}, {%0,%1,%2,%3};"
        : "+f"(c[0]), "+f"(c[1]), "+f"(c[2]), "+f"(c[3])
        : "r"(a[0]), "r"(a[1]), "r"(a[2]), "r"(a[3]), "r"(b[0]), "r"(b[1]));
}

#define ASTR 36   // A smem stride (frag LDS conflict-free: bank = 4g+tg)
#define BSTR 72   // B smem stride (bank = 8tg+col)
#define ATILE (128 * ASTR)
#define BTILE (32 * BSTR)
#define GEMM_SMEM_BYTES (2 * (ATILE + BTILE) * 4)

template <int K>
__launch_bounds__(256)
__global__ void gemm_tf32_kernel(const float* __restrict__ A, const float* __restrict__ Bm,
                                 const float* __restrict__ dinv, __half* __restrict__ C,
                                 int M) {
    extern __shared__ float smem[];
    float* As = smem;                 // [2][128][ASTR]
    float* Bs = smem + 2 * ATILE;     // [2][32][BSTR]

    constexpr int T = K / 32;
    const int tid = threadIdx.x;
    const int lane = tid & 31;
    const int warp = tid >> 5;
    const int wm = (warp & 3) * 32;
    const int wn = (warp >> 2) * 32;
    const int block_row = blockIdx.x * 128;
    const int g = lane >> 2;
    const int tg = lane & 3;

    float acc[2][4][4];
#pragma unroll
    for (int mi = 0; mi < 2; mi++)
#pragma unroll
        for (int na = 0; na < 4; na++)
#pragma unroll
            for (int r = 0; r < 4; r++) acc[mi][na][r] = 0.f;

    // --- prefetch helper (A rows OOB: clamp addr + zero-fill via src-size 0) ---
    auto prefetch = [&](int t, int buf) {
        int k0 = t * 32;
#pragma unroll
        for (int i = 0; i < 4; i++) {
            int idx = tid + i * 256;
            int r = idx >> 3;
            int c4 = (idx & 7) * 4;
            int grow = block_row + r;
            const float* sp = A + (size_t)(grow < M ? grow : 0) * K + k0 + c4;
            unsigned ds = (unsigned)__cvta_generic_to_shared(As + buf * ATILE + r * ASTR + c4);
            int sz = (grow < M) ? 16 : 0;
            asm volatile("cp.async.cg.shared.global [%0], [%1], 16, %2;"
                         :: "r"(ds), "l"(sp), "r"(sz));
        }
#pragma unroll
        for (int i = 0; i < 2; i++) {
            int idx = tid + i * 256;
            int r = idx >> 4;
            int c4 = (idx & 15) * 4;
            const float* sp = Bm + (size_t)(k0 + r) * 64 + c4;
            unsigned ds = (unsigned)__cvta_generic_to_shared(Bs + buf * BTILE + r * BSTR + c4);
            asm volatile("cp.async.cg.shared.global [%0], [%1], 16;" :: "r"(ds), "l"(sp));
        }
        asm volatile("cp.async.commit_group;");
    };

    prefetch(0, 0);

    for (int t = 0; t < T; t++) {
        if (t + 1 < T) {
            prefetch(t + 1, (t + 1) & 1);
            asm volatile("cp.async.wait_group 1;");
        } else {
            asm volatile("cp.async.wait_group 0;");
        }
        __syncthreads();

        const float* At = As + (t & 1) * ATILE;
        const float* Bt = Bs + (t & 1) * BTILE;

#pragma unroll
        for (int ks = 0; ks < 4; ks++) {
            const int kb = ks * 8;
            unsigned a[2][4], b[4][2];
#pragma unroll
            for (int mi = 0; mi < 2; mi++) {
                int row = wm + mi * 16 + g;
                a[mi][0] = f2tf32(At[row * ASTR + kb + tg]);
                a[mi][1] = f2tf32(At[(row + 8) * ASTR + kb + tg]);
                a[mi][2] = f2tf32(At[row * ASTR + kb + tg + 4]);
                a[mi][3] = f2tf32(At[(row + 8) * ASTR + kb + tg + 4]);
            }
#pragma unroll
            for (int na = 0; na < 4; na++) {
                int col = wn + na * 8 + g;
                b[na][0] = f2tf32(Bt[(kb + tg) * BSTR + col]);
                b[na][1] = f2tf32(Bt[(kb + tg + 4) * BSTR + col]);
            }
#pragma unroll
            for (int mi = 0; mi < 2; mi++)
#pragma unroll
                for (int na = 0; na < 4; na++) mma_tf32(acc[mi][na], a[mi], b[na]);
        }
        __syncthreads();
    }

    // epilogue: scale by dinv[row], convert to fp16
#pragma unroll
    for (int mi = 0; mi < 2; mi++) {
        int row_lo = block_row + wm + mi * 16 + g;
        int row_hi = row_lo + 8;
        float s_lo = (row_lo < M) ? dinv[row_lo] : 0.f;
        float s_hi = (row_hi < M) ? dinv[row_hi] : 0.f;
#pragma unroll
        for (int na = 0; na < 4; na++) {
            int col = wn + na * 8 + 2 * tg;
            if (row_lo < M) {
                __half2 h = __floats2half2_rn(acc[mi][na][0] * s_lo, acc[mi][na][1] * s_lo);
                *reinterpret_cast<__half2*>(&C[(size_t)row_lo * 64 + col]) = h;
            }
            if (row_hi < M) {
                __half2 h = __floats2half2_rn(acc[mi][na][2] * s_hi, acc[mi][na][3] * s_hi);
                *reinterpret_cast<__half2*>(&C[(size_t)row_hi * 64 + col]) = h;
            }
        }
    }
}

// ---------------------------------------------------------------------------
// Gather-reduce (fp16 table, padded CSR):
// out[d] = dinv[d]*(h'[d] + sum h'[src]) + bias
// ---------------------------------------------------------------------------
__device__ __forceinline__ void acc_half4(float4& acc, uint2 u) {
    __half2 h0 = *reinterpret_cast<const __half2*>(&u.x);
    __half2 h1 = *reinterpret_cast<const __half2*>(&u.y);
    float2 f0 = __half22float2(h0);
    float2 f1 = __half22float2(h1);
    acc.x += f0.x; acc.y += f0.y; acc.z += f1.x; acc.w += f1.y;
}

template <bool RELU>
__global__ void gather_kernel(const uint2* __restrict__ hs, const int* __restrict__ cnt,
                              const int* __restrict__ srcs, const float* __restrict__ dinv,
                              const float* __restrict__ bias,
                              const int* __restrict__ nspill, const int* __restrict__ spill_d,
                              const int* __restrict__ spill_s,
                              float4* __restrict__ out, int N) {
    int i = blockIdx.x * blockDim.x + threadIdx.x;
    if (i >= N * 16) return;
    int node = i >> 4;
    int lane = i & 15;

    float4 acc = make_float4(0.f, 0.f, 0.f, 0.f);
    acc_half4(acc, hs[(size_t)node * 16 + lane]);  // self-loop term
    const int c = cnt[node];
    int e = node * CAP;
    const int end = e + min(c, CAP);

    for (; e + 4 <= end; e += 4) {
        int s0 = srcs[e], s1 = srcs[e + 1], s2 = srcs[e + 2], s3 = srcs[e + 3];
        uint2 v0 = hs[(size_t)s0 * 16 + lane];
        uint2 v1 = hs[(size_t)s1 * 16 + lane];
        uint2 v2 = hs[(size_t)s2 * 16 + lane];
        uint2 v3 = hs[(size_t)s3 * 16 + lane];
        acc_half4(acc, v0); acc_half4(acc, v1);
        acc_half4(acc, v2); acc_half4(acc, v3);
    }
    for (; e < end; e++) {
        acc_half4(acc, hs[(size_t)srcs[e] * 16 + lane]);
    }

    if (c > CAP) {  // overflow fixup (empty in practice)
        int ns = min(*nspill, MAX_SPILL);
        for (int j = 0; j < ns; j++) {
            if (spill_d[j] == node) acc_half4(acc, hs[(size_t)spill_s[j] * 16 + lane]);
        }
    }

    float dd = dinv[node];
    float4 bv = reinterpret_cast<const float4*>(bias)[lane];
    float r0 = fmaf(acc.x, dd, bv.x);
    float r1 = fmaf(acc.y, dd, bv.y);
    float r2 = fmaf(acc.z, dd, bv.z);
    float r3 = fmaf(acc.w, dd, bv.w);
    if (RELU) {
        r0 = fmaxf(r0, 0.f); r1 = fmaxf(r1, 0.f);
        r2 = fmaxf(r2, 0.f); r3 = fmaxf(r3, 0.f);
    }
    out[(size_t)node * 16 + lane] = make_float4(r0, r1, r2, r3);
}

// ---------------------------------------------------------------------------
// launch
// ---------------------------------------------------------------------------
extern "C" void kernel_launch(void* const* d_in, const int* in_sizes, int n_in,
                              void* d_out, int out_size) {
    const float* x = (const float*)d_in[0];
    const int* edge_index = (const int*)d_in[1];
    const float* W1 = (const float*)d_in[2];
    const float* b1 = (const float*)d_in[3];
    const float* W2 = (const float*)d_in[4];
    const float* b2 = (const float*)d_in[5];
    float* out = (float*)d_out;

    const int IN_CH = 256;
    const int N = in_sizes[0] / IN_CH;  // 100000
    const int E = in_sizes[1] / 2;      // 3200000
    const int* src = edge_index;
    const int* dst = edge_index + E;

    int *cnt, *srcs, *nspill, *spill_d, *spill_s;
    float *dinv, *hid;
    __half *h1, *h2;
    cudaGetSymbolAddress((void**)&cnt, g_cnt);
    cudaGetSymbolAddress((void**)&srcs, g_srcs);
    cudaGetSymbolAddress((void**)&nspill, g_nspill);
    cudaGetSymbolAddress((void**)&spill_d, g_spill_d);
    cudaGetSymbolAddress((void**)&spill_s, g_spill_s);
    cudaGetSymbolAddress((void**)&dinv, g_dinv);
    cudaGetSymbolAddress((void**)&h1, g_h1);
    cudaGetSymbolAddress((void**)&hid, g_hid);
    cudaGetSymbolAddress((void**)&h2, g_h2);

    // allow >48KB dynamic smem (attribute set, not an allocation; idempotent)
    static bool attr_done = false;
    if (!attr_done) {
        cudaFuncSetAttribute(gemm_tf32_kernel<256>,
                             cudaFuncAttributeMaxDynamicSharedMemorySize, GEMM_SMEM_BYTES);
        cudaFuncSetAttribute(gemm_tf32_kernel<64>,
                             cudaFuncAttributeMaxDynamicSharedMemorySize, GEMM_SMEM_BYTES);
        attr_done = true;
    }

    const int T = 256;
    int nBlkN = (N + T - 1) / T;
    int nBlkE = (E + T - 1) / T;
    int nBlkG = (N + 127) / 128;
    int nBlkGa = (N * 16 + T - 1) / T;

    // padded CSR build (single pass)
    zero_cnt_kernel<<<nBlkN, T>>>(cnt, nspill, N);
    hist_scatter_kernel<<<nBlkE, T>>>(src, dst, cnt, srcs, nspill, spill_d, spill_s, E);
    dinv_kernel<<<nBlkN, T>>>(cnt, dinv, N);

    // layer 1
    gemm_tf32_kernel<256><<<nBlkG, T, GEMM_SMEM_BYTES>>>(x, W1, dinv, h1, N);
    gather_kernel<true><<<nBlkGa, T>>>((const uint2*)h1, cnt, srcs, dinv, b1,
                                       nspill, spill_d, spill_s, (float4*)hid, N);

    // layer 2
    gemm_tf32_kernel<64><<<nBlkG, T, GEMM_SMEM_BYTES>>>(hid, W2, dinv, h2, N);
    gather_kernel<false><<<nBlkGa, T>>>((const uint2*)h2, cnt, srcs, dinv, b2,
                                        nspill, spill_d, spill_s, (float4*)out, N);
}